// round 15
// baseline (speedup 1.0000x reference)
#include <cuda_runtime.h>
#include <cuda_bf16.h>
#include <stdint.h>

// Problem constants
#define CB 2
#define CS 2048
#define CD 1024
#define CH 16
#define CDK 64
#define CM (CB*CS)            // 4096 rows in the projection GEMMs

static const size_t OUT_ELEMS  = (size_t)CB*CS*CD;       // 4,194,304
static const size_t ATTN_ELEMS = (size_t)CB*CH*CS*CS;    // 134,217,728

// ---------------------------------------------------------------------------
// Scratch (device globals; uint4-typed for 16B alignment of bf16 views)
// ---------------------------------------------------------------------------
__device__ float g_attn[(size_t)CB*CH*CS*CS];            // fallback attn buffer

__device__ uint4 gXhi_[(size_t)3*CM*CD/8], gXlo_[(size_t)3*CM*CD/8];   // inputs q,k,v
__device__ uint4 gWhi_[(size_t)4*CD*CD/8], gWlo_[(size_t)4*CD*CD/8];   // wq,wk,wv,wo
__device__ uint4 gQhi_[(size_t)CB*CH*CS*CDK/8], gQlo_[(size_t)CB*CH*CS*CDK/8];
__device__ uint4 gKhi_[(size_t)CB*CH*CS*CDK/8], gKlo_[(size_t)CB*CH*CS*CDK/8];
__device__ uint4 gVthi_[(size_t)CB*CH*CS*CDK/8], gVtlo_[(size_t)CB*CH*CS*CDK/8]; // [h][dk][s]
__device__ uint4 gChi_[(size_t)CB*CS*CD/8], gClo_[(size_t)CB*CS*CD/8];           // ctx

#define BF(p) ((__nv_bfloat16*)(p))

// ===========================================================================
// mma.sync bf16 helpers (baseline PTX — legal on compute_103 virtual arch)
// ===========================================================================
__device__ __forceinline__ uint32_t bf2u(__nv_bfloat162 v) { return *reinterpret_cast<uint32_t*>(&v); }

__device__ __forceinline__ void mma16816(float* c, const uint32_t* a, const uint32_t* b) {
    asm volatile(
        "mma.sync.aligned.m16n8k16.row.col.f32.bf16.bf16.f32 "
        "{%0,%1,%2,%3}, {%4,%5,%6,%7}, {%8,%9}, {%0,%1,%2,%3};"
        : "+f"(c[0]), "+f"(c[1]), "+f"(c[2]), "+f"(c[3])
        : "r"(a[0]), "r"(a[1]), "r"(a[2]), "r"(a[3]), "r"(b[0]), "r"(b[1]));
}

__device__ __forceinline__ void split4(float4 v, uint2& hi, uint2& lo) {
    __nv_bfloat16 h0 = __float2bfloat16_rn(v.x);
    __nv_bfloat16 h1 = __float2bfloat16_rn(v.y);
    __nv_bfloat16 h2 = __float2bfloat16_rn(v.z);
    __nv_bfloat16 h3 = __float2bfloat16_rn(v.w);
    float l0 = v.x - __bfloat162float(h0);
    float l1 = v.y - __bfloat162float(h1);
    float l2 = v.z - __bfloat162float(h2);
    float l3 = v.w - __bfloat162float(h3);
    hi = make_uint2(bf2u(__halves2bfloat162(h0, h1)), bf2u(__halves2bfloat162(h2, h3)));
    lo = make_uint2(bf2u(__halves2bfloat162(__float2bfloat16_rn(l0), __float2bfloat16_rn(l1))),
                    bf2u(__halves2bfloat162(__float2bfloat16_rn(l2), __float2bfloat16_rn(l3))));
}
__device__ __forceinline__ void split1(float v, __nv_bfloat16& hi, __nv_bfloat16& lo) {
    hi = __float2bfloat16_rn(v);
    lo = __float2bfloat16_rn(v - __bfloat162float(hi));
}

// ===========================================================================
// Kernel 0: pre-split inputs (z=0..2) and weights (z=3..6) to hi/lo bf16.
// ===========================================================================
__global__ __launch_bounds__(256) void convert_split(
    const float* __restrict__ q, const float* __restrict__ k, const float* __restrict__ v,
    const float* __restrict__ wq, const float* __restrict__ wk, const float* __restrict__ wv,
    const float* __restrict__ wo)
{
    const int z = blockIdx.y;
    const float* srcs[7] = {q, k, v, wq, wk, wv, wo};
    const int nvec = (z < 3 ? CM * CD : CD * CD) / 4;
    const int idx = blockIdx.x * 256 + threadIdx.x;
    if (idx >= nvec) return;
    float4 val = ((const float4*)srcs[z])[idx];
    uint2 hi, lo;
    split4(val, hi, lo);
    uint2* dh;
    uint2* dl;
    if (z < 3) {
        dh = (uint2*)(BF(gXhi_) + (size_t)z * CM * CD);
        dl = (uint2*)(BF(gXlo_) + (size_t)z * CM * CD);
    } else {
        dh = (uint2*)(BF(gWhi_) + (size_t)(z - 3) * CD * CD);
        dl = (uint2*)(BF(gWlo_) + (size_t)(z - 3) * CD * CD);
    }
    dh[idx] = hi;
    dl[idx] = lo;
}

// ===========================================================================
// Split-bf16 GEMM core, preconverted bf16 inputs (DOUBLE-BUFFERED, 1 sync).
// acc[128,128] = A[128,K] * B[128,K]^T.  8 warps 2x4, warp tile 64x32.
// ===========================================================================
#define PADK 40
#define GEMM_SMEM (8 * 128 * PADK * 2)   // bytes

__device__ __forceinline__ void mma_gemm_core_bf(
    const __nv_bfloat16* __restrict__ Ahi_g, const __nv_bfloat16* __restrict__ Alo_g,
    const __nv_bfloat16* __restrict__ Bhi_g, const __nv_bfloat16* __restrict__ Blo_g,
    int ld, int kTotal, __nv_bfloat16* sm, float acc[4][4][4])
{
    const int tid  = threadIdx.x;
    const int wid  = tid >> 5, lane = tid & 31;
    const int wm   = wid & 1,  wn   = wid >> 1;
    const int quad = lane >> 2, tq  = lane & 3;

    const int lrow = tid >> 1;            // tile row loaded by this thread
    const int lk16 = (tid & 1) * 16;      // 16-col half of BK=32

    const __nv_bfloat16* ah = Ahi_g + (size_t)lrow * ld + lk16;
    const __nv_bfloat16* al = Alo_g + (size_t)lrow * ld + lk16;
    const __nv_bfloat16* bh = Bhi_g + (size_t)lrow * ld + lk16;
    const __nv_bfloat16* bl = Blo_g + (size_t)lrow * ld + lk16;

    #pragma unroll
    for (int mi = 0; mi < 4; mi++)
        #pragma unroll
        for (int ni = 0; ni < 4; ni++)
            #pragma unroll
            for (int r = 0; r < 4; r++) acc[mi][ni][r] = 0.f;

    const int STRIDE = 128 * PADK;
    for (int c = 0; c < kTotal / 32; c++) {
        __nv_bfloat16* Ahi = sm + (c & 1) * 4 * STRIDE;
        __nv_bfloat16* Alo = Ahi + STRIDE;
        __nv_bfloat16* Bhi = Alo + STRIDE;
        __nv_bfloat16* Blo = Bhi + STRIDE;

        uint4 vah0 = *(const uint4*)(ah + c * 32);
        uint4 vah1 = *(const uint4*)(ah + c * 32 + 8);
        uint4 val0 = *(const uint4*)(al + c * 32);
        uint4 val1 = *(const uint4*)(al + c * 32 + 8);
        uint4 vbh0 = *(const uint4*)(bh + c * 32);
        uint4 vbh1 = *(const uint4*)(bh + c * 32 + 8);
        uint4 vbl0 = *(const uint4*)(bl + c * 32);
        uint4 vbl1 = *(const uint4*)(bl + c * 32 + 8);

        *(uint4*)(Ahi + lrow * PADK + lk16)     = vah0;
        *(uint4*)(Ahi + lrow * PADK + lk16 + 8) = vah1;
        *(uint4*)(Alo + lrow * PADK + lk16)     = val0;
        *(uint4*)(Alo + lrow * PADK + lk16 + 8) = val1;
        *(uint4*)(Bhi + lrow * PADK + lk16)     = vbh0;
        *(uint4*)(Bhi + lrow * PADK + lk16 + 8) = vbh1;
        *(uint4*)(Blo + lrow * PADK + lk16)     = vbl0;
        *(uint4*)(Blo + lrow * PADK + lk16 + 8) = vbl1;
        __syncthreads();

        #pragma unroll
        for (int k0 = 0; k0 < 32; k0 += 16) {
            uint32_t fa[4][4], fb[4][4], gb[4][2], gl[4][2];
            #pragma unroll
            for (int mi = 0; mi < 4; mi++) {
                const int r0 = wm * 64 + mi * 16 + quad;
                const __nv_bfloat16* p = Ahi + r0 * PADK + k0 + tq * 2;
                const __nv_bfloat16* q = Alo + r0 * PADK + k0 + tq * 2;
                fa[mi][0] = *(const uint32_t*)p;
                fa[mi][1] = *(const uint32_t*)(p + 8 * PADK);
                fa[mi][2] = *(const uint32_t*)(p + 8);
                fa[mi][3] = *(const uint32_t*)(p + 8 * PADK + 8);
                fb[mi][0] = *(const uint32_t*)q;
                fb[mi][1] = *(const uint32_t*)(q + 8 * PADK);
                fb[mi][2] = *(const uint32_t*)(q + 8);
                fb[mi][3] = *(const uint32_t*)(q + 8 * PADK + 8);
            }
            #pragma unroll
            for (int ni = 0; ni < 4; ni++) {
                const int n0 = wn * 32 + ni * 8 + quad;
                const __nv_bfloat16* p = Bhi + n0 * PADK + k0 + tq * 2;
                const __nv_bfloat16* q = Blo + n0 * PADK + k0 + tq * 2;
                gb[ni][0] = *(const uint32_t*)p;
                gb[ni][1] = *(const uint32_t*)(p + 8);
                gl[ni][0] = *(const uint32_t*)q;
                gl[ni][1] = *(const uint32_t*)(q + 8);
            }
            #pragma unroll
            for (int mi = 0; mi < 4; mi++)
                #pragma unroll
                for (int ni = 0; ni < 4; ni++) mma16816(acc[mi][ni], fa[mi], gb[ni]);
            #pragma unroll
            for (int mi = 0; mi < 4; mi++)
                #pragma unroll
                for (int ni = 0; ni < 4; ni++) mma16816(acc[mi][ni], fb[mi], gb[ni]);
            #pragma unroll
            for (int mi = 0; mi < 4; mi++)
                #pragma unroll
                for (int ni = 0; ni < 4; ni++) mma16816(acc[mi][ni], fa[mi], gl[ni]);
        }
    }
}

// ---------------------------------------------------------------------------
// Kernel 1: Q/K/V projections.  Q/K stored split-bf16 [h][s][dk];
// V stored split-bf16 TRANSPOSED [h][dk][s] via smem transpose.
// ---------------------------------------------------------------------------
__global__ __launch_bounds__(256) void proj_mma()
{
    extern __shared__ __nv_bfloat16 smg[];

    const int z = blockIdx.z;
    const int row0 = blockIdx.y * 128, col0 = blockIdx.x * 128;

    float acc[4][4][4];
    mma_gemm_core_bf(
        BF(gXhi_) + (size_t)z * CM * CD + (size_t)row0 * CD,
        BF(gXlo_) + (size_t)z * CM * CD + (size_t)row0 * CD,
        BF(gWhi_) + (size_t)z * CD * CD + (size_t)col0 * CD,
        BF(gWlo_) + (size_t)z * CD * CD + (size_t)col0 * CD,
        CD, CD, smg, acc);

    const int tid  = threadIdx.x;
    const int wid  = tid >> 5, lane = tid & 31;
    const int wm   = wid & 1, wn = wid >> 1;
    const int quad = lane >> 2, tq = lane & 3;

    if (z < 2) {
        __nv_bfloat16* Ohi = z == 0 ? BF(gQhi_) : BF(gKhi_);
        __nv_bfloat16* Olo = z == 0 ? BF(gQlo_) : BF(gKlo_);
        #pragma unroll
        for (int mi = 0; mi < 4; mi++) {
            const int m = row0 + wm * 64 + mi * 16 + quad;
            const int b = m >> 11, s = m & (CS - 1);
            #pragma unroll
            for (int ni = 0; ni < 4; ni++) {
                const int n  = col0 + wn * 32 + ni * 8 + tq * 2;
                const int h  = n >> 6, dk = n & (CDK - 1);
                const size_t i0 = (((size_t)(b * CH + h)) * CS + s)     * CDK + dk;
                const size_t i1 = (((size_t)(b * CH + h)) * CS + s + 8) * CDK + dk;
                __nv_bfloat16 h0, l0, h1, l1;
                split1(acc[mi][ni][0], h0, l0); split1(acc[mi][ni][1], h1, l1);
                *(uint32_t*)&Ohi[i0] = bf2u(__halves2bfloat162(h0, h1));
                *(uint32_t*)&Olo[i0] = bf2u(__halves2bfloat162(l0, l1));
                split1(acc[mi][ni][2], h0, l0); split1(acc[mi][ni][3], h1, l1);
                *(uint32_t*)&Ohi[i1] = bf2u(__halves2bfloat162(h0, h1));
                *(uint32_t*)&Olo[i1] = bf2u(__halves2bfloat162(l0, l1));
            }
        }
    } else {
        // V: transpose through smem scratch (128 n x 128 m fp32, stride 132)
        __syncthreads();                 // all warps done with GEMM smem
        float* ts = (float*)smg;
        #pragma unroll
        for (int mi = 0; mi < 4; mi++) {
            const int ml = wm * 64 + mi * 16 + quad;
            #pragma unroll
            for (int ni = 0; ni < 4; ni++) {
                const int nl = wn * 32 + ni * 8 + tq * 2;
                ts[nl * 132 + ml]           = acc[mi][ni][0];
                ts[(nl + 1) * 132 + ml]     = acc[mi][ni][1];
                ts[nl * 132 + ml + 8]       = acc[mi][ni][2];
                ts[(nl + 1) * 132 + ml + 8] = acc[mi][ni][3];
            }
        }
        __syncthreads();
        const int r    = tid >> 1;           // local n (dk-ish)
        const int half = tid & 1;            // m half
        const int ng   = col0 + r;
        const int h    = ng >> 6, dkv = ng & (CDK - 1);
        const int b    = row0 >> 11;
        const size_t obase = ((size_t)(b * CH + h) * CDK + dkv) * CS + (row0 & (CS - 1)) + half * 64;
        #pragma unroll
        for (int j = 0; j < 16; j++) {
            float4 v = *(float4*)&ts[r * 132 + half * 64 + j * 4];
            uint2 hi, lo;
            split4(v, hi, lo);
            *(uint2*)(BF(gVthi_) + obase + j * 4) = hi;
            *(uint2*)(BF(gVtlo_) + obase + j * 4) = lo;
        }
    }
}

// ---------------------------------------------------------------------------
// Kernel 3: output projection.  out = ctx @ Wo^T + bias (ctx preconverted).
// ---------------------------------------------------------------------------
__global__ __launch_bounds__(256) void outproj_mma(
    const float* __restrict__ bias, float* __restrict__ Out)
{
    extern __shared__ __nv_bfloat16 smg[];

    const int row0 = blockIdx.y * 128, col0 = blockIdx.x * 128;
    float acc[4][4][4];
    mma_gemm_core_bf(
        BF(gChi_) + (size_t)row0 * CD, BF(gClo_) + (size_t)row0 * CD,
        BF(gWhi_) + (size_t)3 * CD * CD + (size_t)col0 * CD,
        BF(gWlo_) + (size_t)3 * CD * CD + (size_t)col0 * CD,
        CD, CD, smg, acc);

    const int wid  = threadIdx.x >> 5, lane = threadIdx.x & 31;
    const int wm   = wid & 1, wn = wid >> 1;
    const int quad = lane >> 2, tq = lane & 3;

    #pragma unroll
    for (int mi = 0; mi < 4; mi++) {
        const int m = row0 + wm * 64 + mi * 16 + quad;
        #pragma unroll
        for (int ni = 0; ni < 4; ni++) {
            const int n = col0 + wn * 32 + ni * 8 + tq * 2;
            const float2 bv = *(const float2*)(bias + n);
            *(float2*)&Out[(size_t)m * CD + n] =
                make_float2(acc[mi][ni][0] + bv.x, acc[mi][ni][1] + bv.y);
            *(float2*)&Out[(size_t)(m + 8) * CD + n] =
                make_float2(acc[mi][ni][2] + bv.x, acc[mi][ni][3] + bv.y);
        }
    }
}

// ===========================================================================
// Kernel 2: fused scores + softmax + context — single pass, preconverted
// bf16 Q/K/V (V pre-transposed), ctx written as split-bf16.
// ===========================================================================
#define PK 72      // padded row stride for Q/K tiles (64 + 8)
#define PW 136     // padded row stride for W/V^T tiles (128 + 8)
#define ASCALE 0.125f
#define SMEM_FUSED 181248

__device__ __forceinline__ void s_mma_64(
    const __nv_bfloat16* Qhi, const __nv_bfloat16* Qlo,
    const __nv_bfloat16* Khi, const __nv_bfloat16* Klo,
    int wm, int wn, int quad, int tq, float sacc[4][4][4])
{
    #pragma unroll
    for (int mi = 0; mi < 4; mi++)
        #pragma unroll
        for (int ni = 0; ni < 4; ni++)
            #pragma unroll
            for (int r = 0; r < 4; r++) sacc[mi][ni][r] = 0.f;

    #pragma unroll
    for (int k0 = 0; k0 < 64; k0 += 16) {
        uint32_t ah[4][4], al[4][4], bh[4][2], bl[4][2];
        #pragma unroll
        for (int mi = 0; mi < 4; mi++) {
            const int r0 = wm * 64 + mi * 16 + quad;
            const __nv_bfloat16* p = Qhi + r0 * PK + k0 + tq * 2;
            const __nv_bfloat16* q = Qlo + r0 * PK + k0 + tq * 2;
            ah[mi][0] = *(const uint32_t*)p;
            ah[mi][1] = *(const uint32_t*)(p + 8 * PK);
            ah[mi][2] = *(const uint32_t*)(p + 8);
            ah[mi][3] = *(const uint32_t*)(p + 8 * PK + 8);
            al[mi][0] = *(const uint32_t*)q;
            al[mi][1] = *(const uint32_t*)(q + 8 * PK);
            al[mi][2] = *(const uint32_t*)(q + 8);
            al[mi][3] = *(const uint32_t*)(q + 8 * PK + 8);
        }
        #pragma unroll
        for (int ni = 0; ni < 4; ni++) {
            const int n0 = wn * 32 + ni * 8 + quad;
            const __nv_bfloat16* p = Khi + n0 * PK + k0 + tq * 2;
            const __nv_bfloat16* q = Klo + n0 * PK + k0 + tq * 2;
            bh[ni][0] = *(const uint32_t*)p;
            bh[ni][1] = *(const uint32_t*)(p + 8);
            bl[ni][0] = *(const uint32_t*)q;
            bl[ni][1] = *(const uint32_t*)(q + 8);
        }
        #pragma unroll
        for (int mi = 0; mi < 4; mi++)
            #pragma unroll
            for (int ni = 0; ni < 4; ni++) mma16816(sacc[mi][ni], ah[mi], bh[ni]);
        #pragma unroll
        for (int mi = 0; mi < 4; mi++)
            #pragma unroll
            for (int ni = 0; ni < 4; ni++) mma16816(sacc[mi][ni], al[mi], bh[ni]);
        #pragma unroll
        for (int mi = 0; mi < 4; mi++)
            #pragma unroll
            for (int ni = 0; ni < 4; ni++) mma16816(sacc[mi][ni], ah[mi], bl[ni]);
    }
}

__global__ __launch_bounds__(256) void fused_attn(float* __restrict__ attn_out, int use_internal)
{
    float* attn = use_internal ? g_attn : attn_out;

    extern __shared__ char dynsm[];
    float* sm_sum  = (float*)dynsm;            // [128] running row sum
    float* sm_aux  = sm_sum + 128;             // [128] 1/sum
    float* sm_part = sm_aux + 128;             // [4][128] partials
    __nv_bfloat16* Qhi = (__nv_bfloat16*)(sm_part + 512);
    __nv_bfloat16* Qlo = Qhi + 128 * PK;
    __nv_bfloat16* Khi = Qlo + 128 * PK;
    __nv_bfloat16* Klo = Khi + 128 * PK;
    __nv_bfloat16* Whi = Klo + 128 * PK;
    __nv_bfloat16* Wlo = Whi + 128 * PW;
    __nv_bfloat16* Vhi = Wlo + 128 * PW;
    __nv_bfloat16* Vlo = Vhi + 64 * PW;

    const int z    = blockIdx.y;
    const int qt   = 15 - blockIdx.x;          // big tiles first
    const int row0 = qt * 128;
    const __nv_bfloat16* Qhg = BF(gQhi_) + (size_t)z * CS * CDK;
    const __nv_bfloat16* Qlg = BF(gQlo_) + (size_t)z * CS * CDK;
    const __nv_bfloat16* Khg = BF(gKhi_) + (size_t)z * CS * CDK;
    const __nv_bfloat16* Klg = BF(gKlo_) + (size_t)z * CS * CDK;
    const __nv_bfloat16* Vhg = BF(gVthi_) + (size_t)z * CDK * CS;
    const __nv_bfloat16* Vlg = BF(gVtlo_) + (size_t)z * CDK * CS;

    const int tid  = threadIdx.x;
    const int wid  = tid >> 5, lane = tid & 31;
    const int wm   = wid & 1,  wn   = wid >> 1;
    const int quad = lane >> 2, tq  = lane & 3;
    const int lrow = tid >> 1, lkq = (tid & 1) * 32;
    const int vr   = tid >> 2, vq  = tid & 3;

    // zero-fill right of causal edge
    {
        const int kend = row0 + 128;
        const int rem4 = (CS - kend) >> 2;
        const int total = 128 * rem4;
        const float4 z4 = make_float4(0.f, 0.f, 0.f, 0.f);
        for (int idx = tid; idx < total; idx += 256) {
            const int r = idx / rem4, c4 = idx - r * rem4;
            *(float4*)&attn[((size_t)z * CS + row0 + r) * CS + kend + c4 * 4] = z4;
        }
    }

    if (tid < 128) sm_sum[tid] = 0.f;

    // load Q tile (bf16 copies)
    {
        const __nv_bfloat16* qh = Qhg + (size_t)(row0 + lrow) * CDK + lkq;
        const __nv_bfloat16* ql = Qlg + (size_t)(row0 + lrow) * CDK + lkq;
        #pragma unroll
        for (int j = 0; j < 4; j++) {
            *(uint4*)(Qhi + lrow * PK + lkq + j * 8) = *(const uint4*)(qh + j * 8);
            *(uint4*)(Qlo + lrow * PK + lkq + j * 8) = *(const uint4*)(ql + j * 8);
        }
    }
    __syncthreads();

    float cacc[4][2][4];
    #pragma unroll
    for (int mi = 0; mi < 4; mi++)
        #pragma unroll
        for (int ni = 0; ni < 2; ni++)
            #pragma unroll
            for (int r = 0; r < 4; r++) cacc[mi][ni][r] = 0.f;

    for (int ck = 0; ck <= qt; ck++) {
        const int kt = ck * 128;
        uint4 kvh[4], kvl[4], vvh[4], vvl[4];
        {
            const __nv_bfloat16* kh = Khg + (size_t)(kt + lrow) * CDK + lkq;
            const __nv_bfloat16* kl = Klg + (size_t)(kt + lrow) * CDK + lkq;
            const __nv_bfloat16* vh = Vhg + (size_t)vr * CS + kt + vq * 32;
            const __nv_bfloat16* vl = Vlg + (size_t)vr * CS + kt + vq * 32;
            #pragma unroll
            for (int j = 0; j < 4; j++) {
                kvh[j] = *(const uint4*)(kh + j * 8);
                kvl[j] = *(const uint4*)(kl + j * 8);
                vvh[j] = *(const uint4*)(vh + j * 8);
                vvl[j] = *(const uint4*)(vl + j * 8);
            }
        }
        __syncthreads();   // prior chunk's MMAs done reading K/V/W smem
        #pragma unroll
        for (int j = 0; j < 4; j++) {
            *(uint4*)(Khi + lrow * PK + lkq + j * 8) = kvh[j];
            *(uint4*)(Klo + lrow * PK + lkq + j * 8) = kvl[j];
            *(uint4*)(Vhi + vr * PW + vq * 32 + j * 8) = vvh[j];
            *(uint4*)(Vlo + vr * PW + vq * 32 + j * 8) = vvl[j];
        }
        __syncthreads();

        float sacc[4][4][4];
        s_mma_64(Qhi, Qlo, Khi, Klo, wm, wn, quad, tq, sacc);

        // w = exp(scale*s), masked lanes exact 0 (diagonal chunk only)
        const int diag = (ck == qt);
        #pragma unroll
        for (int mi = 0; mi < 4; mi++) {
            const int q0A = row0 + wm * 64 + mi * 16 + quad;
            const int q0B = q0A + 8;
            #pragma unroll
            for (int ni = 0; ni < 4; ni++) {
                const int kg = kt + wn * 32 + ni * 8 + tq * 2;
                float w0 = __expf(sacc[mi][ni][0] * ASCALE);
                float w1 = __expf(sacc[mi][ni][1] * ASCALE);
                float w2 = __expf(sacc[mi][ni][2] * ASCALE);
                float w3 = __expf(sacc[mi][ni][3] * ASCALE);
                if (diag) {
                    if (kg     > q0A) w0 = 0.f;
                    if (kg + 1 > q0A) w1 = 0.f;
                    if (kg     > q0B) w2 = 0.f;
                    if (kg + 1 > q0B) w3 = 0.f;
                }
                sacc[mi][ni][0] = w0; sacc[mi][ni][1] = w1;
                sacc[mi][ni][2] = w2; sacc[mi][ni][3] = w3;
            }
        }

        // partial row sums
        #pragma unroll
        for (int mi = 0; mi < 4; mi++) {
            const int rowA = wm * 64 + mi * 16 + quad, rowB = rowA + 8;
            float sA = 0.f, sB = 0.f;
            #pragma unroll
            for (int ni = 0; ni < 4; ni++) {
                sA += sacc[mi][ni][0] + sacc[mi][ni][1];
                sB += sacc[mi][ni][2] + sacc[mi][ni][3];
            }
            #pragma unroll
            for (int o = 1; o <= 2; o <<= 1) {
                sA += __shfl_xor_sync(0xffffffffu, sA, o);
                sB += __shfl_xor_sync(0xffffffffu, sB, o);
            }
            if (tq == 0) { sm_part[wn * 128 + rowA] = sA; sm_part[wn * 128 + rowB] = sB; }
        }
        __syncthreads();
        if (tid < 128)
            sm_sum[tid] += sm_part[tid] + sm_part[128 + tid] + sm_part[256 + tid] + sm_part[384 + tid];

        // write unnormalized w + stage split-bf16
        #pragma unroll
        for (int mi = 0; mi < 4; mi++) {
            const int rowA = wm * 64 + mi * 16 + quad, rowB = rowA + 8;
            const size_t gA = ((size_t)z * CS + row0 + rowA) * CS + kt;
            const size_t gB = ((size_t)z * CS + row0 + rowB) * CS + kt;
            #pragma unroll
            for (int ni = 0; ni < 4; ni++) {
                const int kl = wn * 32 + ni * 8 + tq * 2;
                const float w0 = sacc[mi][ni][0], w1 = sacc[mi][ni][1];
                const float w2 = sacc[mi][ni][2], w3 = sacc[mi][ni][3];
                *(float2*)&attn[gA + kl] = make_float2(w0, w1);
                *(float2*)&attn[gB + kl] = make_float2(w2, w3);
                __nv_bfloat16 h0, l0, h1, l1;
                split1(w0, h0, l0); split1(w1, h1, l1);
                *(uint32_t*)&Whi[rowA * PW + kl] = bf2u(__halves2bfloat162(h0, h1));
                *(uint32_t*)&Wlo[rowA * PW + kl] = bf2u(__halves2bfloat162(l0, l1));
                split1(w2, h0, l0); split1(w3, h1, l1);
                *(uint32_t*)&Whi[rowB * PW + kl] = bf2u(__halves2bfloat162(h0, h1));
                *(uint32_t*)&Wlo[rowB * PW + kl] = bf2u(__halves2bfloat162(l0, l1));
            }
        }
        __syncthreads();

        // ctx_un += W @ V
        #pragma unroll
        for (int k0 = 0; k0 < 128; k0 += 16) {
            uint32_t ah[4][4], al[4][4], bh[2][2], bl[2][2];
            #pragma unroll
            for (int mi = 0; mi < 4; mi++) {
                const int r0 = wm * 64 + mi * 16 + quad;
                const __nv_bfloat16* p = Whi + r0 * PW + k0 + tq * 2;
                const __nv_bfloat16* q = Wlo + r0 * PW + k0 + tq * 2;
                ah[mi][0] = *(const uint32_t*)p;
                ah[mi][1] = *(const uint32_t*)(p + 8 * PW);
                ah[mi][2] = *(const uint32_t*)(p + 8);
                ah[mi][3] = *(const uint32_t*)(p + 8 * PW + 8);
                al[mi][0] = *(const uint32_t*)q;
                al[mi][1] = *(const uint32_t*)(q + 8 * PW);
                al[mi][2] = *(const uint32_t*)(q + 8);
                al[mi][3] = *(const uint32_t*)(q + 8 * PW + 8);
            }
            #pragma unroll
            for (int ni = 0; ni < 2; ni++) {
                const int n0 = wn * 16 + ni * 8 + quad;
                const __nv_bfloat16* p = Vhi + n0 * PW + k0 + tq * 2;
                const __nv_bfloat16* q = Vlo + n0 * PW + k0 + tq * 2;
                bh[ni][0] = *(const uint32_t*)p;
                bh[ni][1] = *(const uint32_t*)(p + 8);
                bl[ni][0] = *(const uint32_t*)q;
                bl[ni][1] = *(const uint32_t*)(q + 8);
            }
            #pragma unroll
            for (int mi = 0; mi < 4; mi++)
                #pragma unroll
                for (int ni = 0; ni < 2; ni++) mma16816(cacc[mi][ni], ah[mi], bh[ni]);
            #pragma unroll
            for (int mi = 0; mi < 4; mi++)
                #pragma unroll
                for (int ni = 0; ni < 2; ni++) mma16816(cacc[mi][ni], al[mi], bh[ni]);
            #pragma unroll
            for (int mi = 0; mi < 4; mi++)
                #pragma unroll
                for (int ni = 0; ni < 2; ni++) mma16816(cacc[mi][ni], ah[mi], bl[ni]);
        }
    }

    __syncthreads();
    if (tid < 128) sm_aux[tid] = 1.f / sm_sum[tid];
    __syncthreads();

    // store ctx = ctx_un * inv_sum as split-bf16 in [b,s,h,dk]
    const int b = z >> 4, h = z & (CH - 1);
    #pragma unroll
    for (int mi = 0; mi < 4; mi++) {
        const int rloc = wm * 64 + mi * 16 + quad;
        const int q0 = row0 + rloc;
        const float iA = sm_aux[rloc], iB = sm_aux[rloc + 8];
        #pragma unroll
        for (int ni = 0; ni < 2; ni++) {
            const int dk = wn * 16 + ni * 8 + tq * 2;
            const size_t i0 = (((size_t)b * CS + q0) * CH + h) * CDK + dk;
            const size_t i1 = (((size_t)b * CS + q0 + 8) * CH + h) * CDK + dk;
            __nv_bfloat16 h0, l0, h1, l1;
            split1(cacc[mi][ni][0] * iA, h0, l0); split1(cacc[mi][ni][1] * iA, h1, l1);
            *(uint32_t*)&BF(gChi_)[i0] = bf2u(__halves2bfloat162(h0, h1));
            *(uint32_t*)&BF(gClo_)[i0] = bf2u(__halves2bfloat162(l0, l1));
            split1(cacc[mi][ni][2] * iB, h0, l0); split1(cacc[mi][ni][3] * iB, h1, l1);
            *(uint32_t*)&BF(gChi_)[i1] = bf2u(__halves2bfloat162(h0, h1));
            *(uint32_t*)&BF(gClo_)[i1] = bf2u(__halves2bfloat162(l0, l1));
        }
    }

    // rescale this block's attn rows (L2-warm)
    {
        const int c4n = (qt + 1) * 32;
        for (int r = wid; r < 128; r += 8) {
            const float inv = sm_aux[r];
            float4* base = (float4*)&attn[((size_t)z * CS + row0 + r) * CS];
            for (int c = lane; c < c4n; c += 32) {
                float4 v = base[c];
                base[c] = make_float4(v.x * inv, v.y * inv, v.z * inv, v.w * inv);
            }
        }
    }
}

// ---------------------------------------------------------------------------
extern "C" void kernel_launch(void* const* d_in, const int* in_sizes, int n_in,
                              void* d_out, int out_size)
{
    const float* query = (const float*)d_in[0];
    const float* key   = (const float*)d_in[1];
    const float* value = (const float*)d_in[2];
    // d_in[3] = mask (causal by construction; unused)
    const float* w_q = (const float*)d_in[4];
    const float* w_k = (const float*)d_in[5];
    const float* w_v = (const float*)d_in[6];
    const float* w_o = (const float*)d_in[7];
    const float* b_o = (const float*)d_in[8];

    float* out = (float*)d_out;
    const int attn_in_out = ((size_t)out_size >= OUT_ELEMS + ATTN_ELEMS) ? 1 : 0;
    float* attn_ptr = attn_in_out ? (out + OUT_ELEMS) : nullptr;
    const int use_internal = attn_in_out ? 0 : 1;

    cudaFuncSetAttribute(proj_mma,    cudaFuncAttributeMaxDynamicSharedMemorySize, GEMM_SMEM);
    cudaFuncSetAttribute(outproj_mma, cudaFuncAttributeMaxDynamicSharedMemorySize, GEMM_SMEM);
    cudaFuncSetAttribute(fused_attn,  cudaFuncAttributeMaxDynamicSharedMemorySize, SMEM_FUSED);

    // 0. pre-split inputs + weights to hi/lo bf16
    convert_split<<<dim3(4096, 7), 256>>>(query, key, value, w_q, w_k, w_v, w_o);

    // 1. Q/K/V projections (bf16-preconverted mainloop; V stored transposed)
    proj_mma<<<dim3(CD/128, CM/128, 3), 256, GEMM_SMEM>>>();

    // 2. fused single-pass attention
    fused_attn<<<dim3(16, CB*CH), 256, SMEM_FUSED>>>(attn_ptr, use_internal);

    // 3. output projection + bias
    outproj_mma<<<dim3(CD/128, CM/128), 256, GEMM_SMEM>>>(b_o, out);
}

// round 16
// speedup vs baseline: 1.1275x; 1.1275x over previous
#include <cuda_runtime.h>
#include <cuda_bf16.h>
#include <stdint.h>

// Problem constants
#define CB 2
#define CS 2048
#define CD 1024
#define CH 16
#define CDK 64
#define CM (CB*CS)            // 4096 rows in the projection GEMMs

static const size_t OUT_ELEMS  = (size_t)CB*CS*CD;       // 4,194,304
static const size_t ATTN_ELEMS = (size_t)CB*CH*CS*CS;    // 134,217,728

// ---------------------------------------------------------------------------
// Scratch (device globals; uint4-typed for 16B alignment of bf16 views)
// ---------------------------------------------------------------------------
__device__ float g_attn[(size_t)CB*CH*CS*CS];            // fallback attn buffer

__device__ uint4 gXhi_[(size_t)3*CM*CD/8], gXlo_[(size_t)3*CM*CD/8];   // inputs q,k,v
__device__ uint4 gWhi_[(size_t)4*CD*CD/8], gWlo_[(size_t)4*CD*CD/8];   // wq,wk,wv,wo
__device__ uint4 gQhi_[(size_t)CB*CH*CS*CDK/8], gQlo_[(size_t)CB*CH*CS*CDK/8];
__device__ uint4 gKhi_[(size_t)CB*CH*CS*CDK/8], gKlo_[(size_t)CB*CH*CS*CDK/8];
__device__ uint4 gVthi_[(size_t)CB*CH*CS*CDK/8], gVtlo_[(size_t)CB*CH*CS*CDK/8]; // [h][dk][s]
__device__ uint4 gChi_[(size_t)CB*CS*CD/8], gClo_[(size_t)CB*CS*CD/8];           // ctx

#define BF(p) ((__nv_bfloat16*)(p))

// ===========================================================================
// mma.sync bf16 + cp.async helpers (baseline PTX — legal on compute_103)
// ===========================================================================
__device__ __forceinline__ uint32_t bf2u(__nv_bfloat162 v) { return *reinterpret_cast<uint32_t*>(&v); }

__device__ __forceinline__ void mma16816(float* c, const uint32_t* a, const uint32_t* b) {
    asm volatile(
        "mma.sync.aligned.m16n8k16.row.col.f32.bf16.bf16.f32 "
        "{%0,%1,%2,%3}, {%4,%5,%6,%7}, {%8,%9}, {%0,%1,%2,%3};"
        : "+f"(c[0]), "+f"(c[1]), "+f"(c[2]), "+f"(c[3])
        : "r"(a[0]), "r"(a[1]), "r"(a[2]), "r"(a[3]), "r"(b[0]), "r"(b[1]));
}

__device__ __forceinline__ uint32_t smem_u32(const void* p) {
    uint32_t a;
    asm("{ .reg .u64 t; cvta.to.shared.u64 t, %1; cvt.u32.u64 %0, t; }" : "=r"(a) : "l"(p));
    return a;
}
__device__ __forceinline__ void cp_async16(uint32_t saddr, const void* gptr) {
    asm volatile("cp.async.cg.shared.global [%0], [%1], 16;" :: "r"(saddr), "l"(gptr));
}
__device__ __forceinline__ void cp_commit() { asm volatile("cp.async.commit_group;" ::: "memory"); }
template <int N> __device__ __forceinline__ void cp_wait() {
    asm volatile("cp.async.wait_group %0;" :: "n"(N) : "memory");
}

__device__ __forceinline__ void split4(float4 v, uint2& hi, uint2& lo) {
    __nv_bfloat16 h0 = __float2bfloat16_rn(v.x);
    __nv_bfloat16 h1 = __float2bfloat16_rn(v.y);
    __nv_bfloat16 h2 = __float2bfloat16_rn(v.z);
    __nv_bfloat16 h3 = __float2bfloat16_rn(v.w);
    float l0 = v.x - __bfloat162float(h0);
    float l1 = v.y - __bfloat162float(h1);
    float l2 = v.z - __bfloat162float(h2);
    float l3 = v.w - __bfloat162float(h3);
    hi = make_uint2(bf2u(__halves2bfloat162(h0, h1)), bf2u(__halves2bfloat162(h2, h3)));
    lo = make_uint2(bf2u(__halves2bfloat162(__float2bfloat16_rn(l0), __float2bfloat16_rn(l1))),
                    bf2u(__halves2bfloat162(__float2bfloat16_rn(l2), __float2bfloat16_rn(l3))));
}
__device__ __forceinline__ void split1(float v, __nv_bfloat16& hi, __nv_bfloat16& lo) {
    hi = __float2bfloat16_rn(v);
    lo = __float2bfloat16_rn(v - __bfloat162float(hi));
}

// ===========================================================================
// Kernel 0: pre-split inputs (z=0..2) and weights (z=3..6) to hi/lo bf16.
// ===========================================================================
__global__ __launch_bounds__(256) void convert_split(
    const float* __restrict__ q, const float* __restrict__ k, const float* __restrict__ v,
    const float* __restrict__ wq, const float* __restrict__ wk, const float* __restrict__ wv,
    const float* __restrict__ wo)
{
    const int z = blockIdx.y;
    const float* srcs[7] = {q, k, v, wq, wk, wv, wo};
    const int nvec = (z < 3 ? CM * CD : CD * CD) / 4;
    const int idx = blockIdx.x * 256 + threadIdx.x;
    if (idx >= nvec) return;
    float4 val = ((const float4*)srcs[z])[idx];
    uint2 hi, lo;
    split4(val, hi, lo);
    uint2* dh;
    uint2* dl;
    if (z < 3) {
        dh = (uint2*)(BF(gXhi_) + (size_t)z * CM * CD);
        dl = (uint2*)(BF(gXlo_) + (size_t)z * CM * CD);
    } else {
        dh = (uint2*)(BF(gWhi_) + (size_t)(z - 3) * CD * CD);
        dl = (uint2*)(BF(gWlo_) + (size_t)(z - 3) * CD * CD);
    }
    dh[idx] = hi;
    dl[idx] = lo;
}

// ===========================================================================
// Split-bf16 GEMM core: cp.async 2-stage pipeline (LDGSTS, no reg staging).
// acc[128,128] = A[128,K] * B[128,K]^T.  8 warps 2x4, warp tile 64x32.
// ===========================================================================
#define PADK 40
#define SB_BYTES (128 * PADK * 2)          // one hi/lo array, bytes
#define GEMM_SMEM (8 * SB_BYTES)           // 2 stages x 4 arrays

__device__ __forceinline__ void mma_gemm_core_bf(
    const __nv_bfloat16* __restrict__ Ahi_g, const __nv_bfloat16* __restrict__ Alo_g,
    const __nv_bfloat16* __restrict__ Bhi_g, const __nv_bfloat16* __restrict__ Blo_g,
    int ld, int kTotal, __nv_bfloat16* sm, float acc[4][4][4])
{
    const int tid  = threadIdx.x;
    const int wid  = tid >> 5, lane = tid & 31;
    const int wm   = wid & 1,  wn   = wid >> 1;
    const int quad = lane >> 2, tq  = lane & 3;

    const int lrow = tid >> 1;            // tile row loaded by this thread
    const int lk16 = (tid & 1) * 16;      // 16-col half of BK=32

    const __nv_bfloat16* ah = Ahi_g + (size_t)lrow * ld + lk16;
    const __nv_bfloat16* al = Alo_g + (size_t)lrow * ld + lk16;
    const __nv_bfloat16* bh = Bhi_g + (size_t)lrow * ld + lk16;
    const __nv_bfloat16* bl = Blo_g + (size_t)lrow * ld + lk16;

    const uint32_t sbase = smem_u32(sm);
    const uint32_t soff  = (uint32_t)(lrow * PADK + lk16) * 2;   // bytes, 16B-aligned

    #pragma unroll
    for (int mi = 0; mi < 4; mi++)
        #pragma unroll
        for (int ni = 0; ni < 4; ni++)
            #pragma unroll
            for (int r = 0; r < 4; r++) acc[mi][ni][r] = 0.f;

    const int nch = kTotal / 32;

    // prefetch chunk 0 into stage 0
    {
        const uint32_t s0 = sbase + soff;
        cp_async16(s0,                ah);
        cp_async16(s0 + 16,           ah + 8);
        cp_async16(s0 + SB_BYTES,     al);
        cp_async16(s0 + SB_BYTES+16,  al + 8);
        cp_async16(s0 + 2*SB_BYTES,   bh);
        cp_async16(s0 + 2*SB_BYTES+16,bh + 8);
        cp_async16(s0 + 3*SB_BYTES,   bl);
        cp_async16(s0 + 3*SB_BYTES+16,bl + 8);
        cp_commit();
    }

    const int STRIDE = 128 * PADK;
    for (int c = 0; c < nch; c++) {
        if (c + 1 < nch) {     // prefetch next chunk into the other stage
            const uint32_t s1 = sbase + ((c + 1) & 1) * 4 * SB_BYTES + soff;
            const int g = (c + 1) * 32;
            cp_async16(s1,                 ah + g);
            cp_async16(s1 + 16,            ah + g + 8);
            cp_async16(s1 + SB_BYTES,      al + g);
            cp_async16(s1 + SB_BYTES+16,   al + g + 8);
            cp_async16(s1 + 2*SB_BYTES,    bh + g);
            cp_async16(s1 + 2*SB_BYTES+16, bh + g + 8);
            cp_async16(s1 + 3*SB_BYTES,    bl + g);
            cp_async16(s1 + 3*SB_BYTES+16, bl + g + 8);
            cp_commit();
            cp_wait<1>();      // chunk c arrived; c+1 in flight
        } else {
            cp_wait<0>();
        }
        __syncthreads();

        __nv_bfloat16* Ahi = sm + (c & 1) * 4 * STRIDE;
        __nv_bfloat16* Alo = Ahi + STRIDE;
        __nv_bfloat16* Bhi = Alo + STRIDE;
        __nv_bfloat16* Blo = Bhi + STRIDE;

        #pragma unroll
        for (int k0 = 0; k0 < 32; k0 += 16) {
            uint32_t fa[4][4], fb[4][4], gb[4][2], gl[4][2];
            #pragma unroll
            for (int mi = 0; mi < 4; mi++) {
                const int r0 = wm * 64 + mi * 16 + quad;
                const __nv_bfloat16* p = Ahi + r0 * PADK + k0 + tq * 2;
                const __nv_bfloat16* q = Alo + r0 * PADK + k0 + tq * 2;
                fa[mi][0] = *(const uint32_t*)p;
                fa[mi][1] = *(const uint32_t*)(p + 8 * PADK);
                fa[mi][2] = *(const uint32_t*)(p + 8);
                fa[mi][3] = *(const uint32_t*)(p + 8 * PADK + 8);
                fb[mi][0] = *(const uint32_t*)q;
                fb[mi][1] = *(const uint32_t*)(q + 8 * PADK);
                fb[mi][2] = *(const uint32_t*)(q + 8);
                fb[mi][3] = *(const uint32_t*)(q + 8 * PADK + 8);
            }
            #pragma unroll
            for (int ni = 0; ni < 4; ni++) {
                const int n0 = wn * 32 + ni * 8 + quad;
                const __nv_bfloat16* p = Bhi + n0 * PADK + k0 + tq * 2;
                const __nv_bfloat16* q = Blo + n0 * PADK + k0 + tq * 2;
                gb[ni][0] = *(const uint32_t*)p;
                gb[ni][1] = *(const uint32_t*)(p + 8);
                gl[ni][0] = *(const uint32_t*)q;
                gl[ni][1] = *(const uint32_t*)(q + 8);
            }
            #pragma unroll
            for (int mi = 0; mi < 4; mi++)
                #pragma unroll
                for (int ni = 0; ni < 4; ni++) mma16816(acc[mi][ni], fa[mi], gb[ni]);
            #pragma unroll
            for (int mi = 0; mi < 4; mi++)
                #pragma unroll
                for (int ni = 0; ni < 4; ni++) mma16816(acc[mi][ni], fb[mi], gb[ni]);
            #pragma unroll
            for (int mi = 0; mi < 4; mi++)
                #pragma unroll
                for (int ni = 0; ni < 4; ni++) mma16816(acc[mi][ni], fa[mi], gl[ni]);
        }
        __syncthreads();       // all warps done reading stage (c&1) before refill
    }
}

// ---------------------------------------------------------------------------
// Kernel 1: Q/K/V projections.  Q/K stored split-bf16 [h][s][dk];
// V stored split-bf16 TRANSPOSED [h][dk][s] via smem transpose.
// ---------------------------------------------------------------------------
__global__ __launch_bounds__(256) void proj_mma()
{
    extern __shared__ __nv_bfloat16 smg[];

    const int z = blockIdx.z;
    const int row0 = blockIdx.y * 128, col0 = blockIdx.x * 128;

    float acc[4][4][4];
    mma_gemm_core_bf(
        BF(gXhi_) + (size_t)z * CM * CD + (size_t)row0 * CD,
        BF(gXlo_) + (size_t)z * CM * CD + (size_t)row0 * CD,
        BF(gWhi_) + (size_t)z * CD * CD + (size_t)col0 * CD,
        BF(gWlo_) + (size_t)z * CD * CD + (size_t)col0 * CD,
        CD, CD, smg, acc);

    const int tid  = threadIdx.x;
    const int wid  = tid >> 5, lane = tid & 31;
    const int wm   = wid & 1, wn = wid >> 1;
    const int quad = lane >> 2, tq = lane & 3;

    if (z < 2) {
        __nv_bfloat16* Ohi = z == 0 ? BF(gQhi_) : BF(gKhi_);
        __nv_bfloat16* Olo = z == 0 ? BF(gQlo_) : BF(gKlo_);
        #pragma unroll
        for (int mi = 0; mi < 4; mi++) {
            const int m = row0 + wm * 64 + mi * 16 + quad;
            const int b = m >> 11, s = m & (CS - 1);
            #pragma unroll
            for (int ni = 0; ni < 4; ni++) {
                const int n  = col0 + wn * 32 + ni * 8 + tq * 2;
                const int h  = n >> 6, dk = n & (CDK - 1);
                const size_t i0 = (((size_t)(b * CH + h)) * CS + s)     * CDK + dk;
                const size_t i1 = (((size_t)(b * CH + h)) * CS + s + 8) * CDK + dk;
                __nv_bfloat16 h0, l0, h1, l1;
                split1(acc[mi][ni][0], h0, l0); split1(acc[mi][ni][1], h1, l1);
                *(uint32_t*)&Ohi[i0] = bf2u(__halves2bfloat162(h0, h1));
                *(uint32_t*)&Olo[i0] = bf2u(__halves2bfloat162(l0, l1));
                split1(acc[mi][ni][2], h0, l0); split1(acc[mi][ni][3], h1, l1);
                *(uint32_t*)&Ohi[i1] = bf2u(__halves2bfloat162(h0, h1));
                *(uint32_t*)&Olo[i1] = bf2u(__halves2bfloat162(l0, l1));
            }
        }
    } else {
        // V: transpose through smem scratch (128 n x 128 m fp32, stride 132)
        __syncthreads();                 // all warps done with GEMM smem
        float* ts = (float*)smg;
        #pragma unroll
        for (int mi = 0; mi < 4; mi++) {
            const int ml = wm * 64 + mi * 16 + quad;
            #pragma unroll
            for (int ni = 0; ni < 4; ni++) {
                const int nl = wn * 32 + ni * 8 + tq * 2;
                ts[nl * 132 + ml]           = acc[mi][ni][0];
                ts[(nl + 1) * 132 + ml]     = acc[mi][ni][1];
                ts[nl * 132 + ml + 8]       = acc[mi][ni][2];
                ts[(nl + 1) * 132 + ml + 8] = acc[mi][ni][3];
            }
        }
        __syncthreads();
        const int r    = tid >> 1;           // local n (dk-ish)
        const int half = tid & 1;            // m half
        const int ng   = col0 + r;
        const int h    = ng >> 6, dkv = ng & (CDK - 1);
        const int b    = row0 >> 11;
        const size_t obase = ((size_t)(b * CH + h) * CDK + dkv) * CS + (row0 & (CS - 1)) + half * 64;
        #pragma unroll
        for (int j = 0; j < 16; j++) {
            float4 v = *(float4*)&ts[r * 132 + half * 64 + j * 4];
            uint2 hi, lo;
            split4(v, hi, lo);
            *(uint2*)(BF(gVthi_) + obase + j * 4) = hi;
            *(uint2*)(BF(gVtlo_) + obase + j * 4) = lo;
        }
    }
}

// ---------------------------------------------------------------------------
// Kernel 3: output projection.  out = ctx @ Wo^T + bias (ctx preconverted).
// ---------------------------------------------------------------------------
__global__ __launch_bounds__(256) void outproj_mma(
    const float* __restrict__ bias, float* __restrict__ Out)
{
    extern __shared__ __nv_bfloat16 smg[];

    const int row0 = blockIdx.y * 128, col0 = blockIdx.x * 128;
    float acc[4][4][4];
    mma_gemm_core_bf(
        BF(gChi_) + (size_t)row0 * CD, BF(gClo_) + (size_t)row0 * CD,
        BF(gWhi_) + (size_t)3 * CD * CD + (size_t)col0 * CD,
        BF(gWlo_) + (size_t)3 * CD * CD + (size_t)col0 * CD,
        CD, CD, smg, acc);

    const int wid  = threadIdx.x >> 5, lane = threadIdx.x & 31;
    const int wm   = wid & 1, wn = wid >> 1;
    const int quad = lane >> 2, tq = lane & 3;

    #pragma unroll
    for (int mi = 0; mi < 4; mi++) {
        const int m = row0 + wm * 64 + mi * 16 + quad;
        #pragma unroll
        for (int ni = 0; ni < 4; ni++) {
            const int n = col0 + wn * 32 + ni * 8 + tq * 2;
            const float2 bv = *(const float2*)(bias + n);
            *(float2*)&Out[(size_t)m * CD + n] =
                make_float2(acc[mi][ni][0] + bv.x, acc[mi][ni][1] + bv.y);
            *(float2*)&Out[(size_t)(m + 8) * CD + n] =
                make_float2(acc[mi][ni][2] + bv.x, acc[mi][ni][3] + bv.y);
        }
    }
}

// ===========================================================================
// Kernel 2: fused scores + softmax + context — single pass, preconverted
// bf16 Q/K/V (V pre-transposed), ctx written as split-bf16.
// ===========================================================================
#define PK 72      // padded row stride for Q/K tiles (64 + 8)
#define PW 136     // padded row stride for W/V^T tiles (128 + 8)
#define ASCALE 0.125f
#define SMEM_FUSED 181248

__device__ __forceinline__ void s_mma_64(
    const __nv_bfloat16* Qhi, const __nv_bfloat16* Qlo,
    const __nv_bfloat16* Khi, const __nv_bfloat16* Klo,
    int wm, int wn, int quad, int tq, float sacc[4][4][4])
{
    #pragma unroll
    for (int mi = 0; mi < 4; mi++)
        #pragma unroll
        for (int ni = 0; ni < 4; ni++)
            #pragma unroll
            for (int r = 0; r < 4; r++) sacc[mi][ni][r] = 0.f;

    #pragma unroll
    for (int k0 = 0; k0 < 64; k0 += 16) {
        uint32_t ah[4][4], al[4][4], bh[4][2], bl[4][2];
        #pragma unroll
        for (int mi = 0; mi < 4; mi++) {
            const int r0 = wm * 64 + mi * 16 + quad;
            const __nv_bfloat16* p = Qhi + r0 * PK + k0 + tq * 2;
            const __nv_bfloat16* q = Qlo + r0 * PK + k0 + tq * 2;
            ah[mi][0] = *(const uint32_t*)p;
            ah[mi][1] = *(const uint32_t*)(p + 8 * PK);
            ah[mi][2] = *(const uint32_t*)(p + 8);
            ah[mi][3] = *(const uint32_t*)(p + 8 * PK + 8);
            al[mi][0] = *(const uint32_t*)q;
            al[mi][1] = *(const uint32_t*)(q + 8 * PK);
            al[mi][2] = *(const uint32_t*)(q + 8);
            al[mi][3] = *(const uint32_t*)(q + 8 * PK + 8);
        }
        #pragma unroll
        for (int ni = 0; ni < 4; ni++) {
            const int n0 = wn * 32 + ni * 8 + quad;
            const __nv_bfloat16* p = Khi + n0 * PK + k0 + tq * 2;
            const __nv_bfloat16* q = Klo + n0 * PK + k0 + tq * 2;
            bh[ni][0] = *(const uint32_t*)p;
            bh[ni][1] = *(const uint32_t*)(p + 8);
            bl[ni][0] = *(const uint32_t*)q;
            bl[ni][1] = *(const uint32_t*)(q + 8);
        }
        #pragma unroll
        for (int mi = 0; mi < 4; mi++)
            #pragma unroll
            for (int ni = 0; ni < 4; ni++) mma16816(sacc[mi][ni], ah[mi], bh[ni]);
        #pragma unroll
        for (int mi = 0; mi < 4; mi++)
            #pragma unroll
            for (int ni = 0; ni < 4; ni++) mma16816(sacc[mi][ni], al[mi], bh[ni]);
        #pragma unroll
        for (int mi = 0; mi < 4; mi++)
            #pragma unroll
            for (int ni = 0; ni < 4; ni++) mma16816(sacc[mi][ni], ah[mi], bl[ni]);
    }
}

__global__ __launch_bounds__(256) void fused_attn(float* __restrict__ attn_out, int use_internal)
{
    float* attn = use_internal ? g_attn : attn_out;

    extern __shared__ char dynsm[];
    float* sm_sum  = (float*)dynsm;            // [128] running row sum
    float* sm_aux  = sm_sum + 128;             // [128] 1/sum
    float* sm_part = sm_aux + 128;             // [4][128] partials
    __nv_bfloat16* Qhi = (__nv_bfloat16*)(sm_part + 512);
    __nv_bfloat16* Qlo = Qhi + 128 * PK;
    __nv_bfloat16* Khi = Qlo + 128 * PK;
    __nv_bfloat16* Klo = Khi + 128 * PK;
    __nv_bfloat16* Whi = Klo + 128 * PK;
    __nv_bfloat16* Wlo = Whi + 128 * PW;
    __nv_bfloat16* Vhi = Wlo + 128 * PW;
    __nv_bfloat16* Vlo = Vhi + 64 * PW;

    const int z    = blockIdx.y;
    const int qt   = 15 - blockIdx.x;          // big tiles first
    const int row0 = qt * 128;
    const __nv_bfloat16* Qhg = BF(gQhi_) + (size_t)z * CS * CDK;
    const __nv_bfloat16* Qlg = BF(gQlo_) + (size_t)z * CS * CDK;
    const __nv_bfloat16* Khg = BF(gKhi_) + (size_t)z * CS * CDK;
    const __nv_bfloat16* Klg = BF(gKlo_) + (size_t)z * CS * CDK;
    const __nv_bfloat16* Vhg = BF(gVthi_) + (size_t)z * CDK * CS;
    const __nv_bfloat16* Vlg = BF(gVtlo_) + (size_t)z * CDK * CS;

    const int tid  = threadIdx.x;
    const int wid  = tid >> 5, lane = tid & 31;
    const int wm   = wid & 1,  wn   = wid >> 1;
    const int quad = lane >> 2, tq  = lane & 3;
    const int lrow = tid >> 1, lkq = (tid & 1) * 32;
    const int vr   = tid >> 2, vq  = tid & 3;

    // zero-fill right of causal edge
    {
        const int kend = row0 + 128;
        const int rem4 = (CS - kend) >> 2;
        const int total = 128 * rem4;
        const float4 z4 = make_float4(0.f, 0.f, 0.f, 0.f);
        for (int idx = tid; idx < total; idx += 256) {
            const int r = idx / rem4, c4 = idx - r * rem4;
            *(float4*)&attn[((size_t)z * CS + row0 + r) * CS + kend + c4 * 4] = z4;
        }
    }

    if (tid < 128) sm_sum[tid] = 0.f;

    // load Q tile (bf16 copies)
    {
        const __nv_bfloat16* qh = Qhg + (size_t)(row0 + lrow) * CDK + lkq;
        const __nv_bfloat16* ql = Qlg + (size_t)(row0 + lrow) * CDK + lkq;
        #pragma unroll
        for (int j = 0; j < 4; j++) {
            *(uint4*)(Qhi + lrow * PK + lkq + j * 8) = *(const uint4*)(qh + j * 8);
            *(uint4*)(Qlo + lrow * PK + lkq + j * 8) = *(const uint4*)(ql + j * 8);
        }
    }
    __syncthreads();

    float cacc[4][2][4];
    #pragma unroll
    for (int mi = 0; mi < 4; mi++)
        #pragma unroll
        for (int ni = 0; ni < 2; ni++)
            #pragma unroll
            for (int r = 0; r < 4; r++) cacc[mi][ni][r] = 0.f;

    for (int ck = 0; ck <= qt; ck++) {
        const int kt = ck * 128;
        uint4 kvh[4], kvl[4], vvh[4], vvl[4];
        {
            const __nv_bfloat16* kh = Khg + (size_t)(kt + lrow) * CDK + lkq;
            const __nv_bfloat16* kl = Klg + (size_t)(kt + lrow) * CDK + lkq;
            const __nv_bfloat16* vh = Vhg + (size_t)vr * CS + kt + vq * 32;
            const __nv_bfloat16* vl = Vlg + (size_t)vr * CS + kt + vq * 32;
            #pragma unroll
            for (int j = 0; j < 4; j++) {
                kvh[j] = *(const uint4*)(kh + j * 8);
                kvl[j] = *(const uint4*)(kl + j * 8);
                vvh[j] = *(const uint4*)(vh + j * 8);
                vvl[j] = *(const uint4*)(vl + j * 8);
            }
        }
        __syncthreads();   // prior chunk's MMAs done reading K/V/W smem
        #pragma unroll
        for (int j = 0; j < 4; j++) {
            *(uint4*)(Khi + lrow * PK + lkq + j * 8) = kvh[j];
            *(uint4*)(Klo + lrow * PK + lkq + j * 8) = kvl[j];
            *(uint4*)(Vhi + vr * PW + vq * 32 + j * 8) = vvh[j];
            *(uint4*)(Vlo + vr * PW + vq * 32 + j * 8) = vvl[j];
        }
        __syncthreads();

        float sacc[4][4][4];
        s_mma_64(Qhi, Qlo, Khi, Klo, wm, wn, quad, tq, sacc);

        // w = exp(scale*s), masked lanes exact 0 (diagonal chunk only)
        const int diag = (ck == qt);
        #pragma unroll
        for (int mi = 0; mi < 4; mi++) {
            const int q0A = row0 + wm * 64 + mi * 16 + quad;
            const int q0B = q0A + 8;
            #pragma unroll
            for (int ni = 0; ni < 4; ni++) {
                const int kg = kt + wn * 32 + ni * 8 + tq * 2;
                float w0 = __expf(sacc[mi][ni][0] * ASCALE);
                float w1 = __expf(sacc[mi][ni][1] * ASCALE);
                float w2 = __expf(sacc[mi][ni][2] * ASCALE);
                float w3 = __expf(sacc[mi][ni][3] * ASCALE);
                if (diag) {
                    if (kg     > q0A) w0 = 0.f;
                    if (kg + 1 > q0A) w1 = 0.f;
                    if (kg     > q0B) w2 = 0.f;
                    if (kg + 1 > q0B) w3 = 0.f;
                }
                sacc[mi][ni][0] = w0; sacc[mi][ni][1] = w1;
                sacc[mi][ni][2] = w2; sacc[mi][ni][3] = w3;
            }
        }

        // partial row sums
        #pragma unroll
        for (int mi = 0; mi < 4; mi++) {
            const int rowA = wm * 64 + mi * 16 + quad, rowB = rowA + 8;
            float sA = 0.f, sB = 0.f;
            #pragma unroll
            for (int ni = 0; ni < 4; ni++) {
                sA += sacc[mi][ni][0] + sacc[mi][ni][1];
                sB += sacc[mi][ni][2] + sacc[mi][ni][3];
            }
            #pragma unroll
            for (int o = 1; o <= 2; o <<= 1) {
                sA += __shfl_xor_sync(0xffffffffu, sA, o);
                sB += __shfl_xor_sync(0xffffffffu, sB, o);
            }
            if (tq == 0) { sm_part[wn * 128 + rowA] = sA; sm_part[wn * 128 + rowB] = sB; }
        }
        __syncthreads();
        if (tid < 128)
            sm_sum[tid] += sm_part[tid] + sm_part[128 + tid] + sm_part[256 + tid] + sm_part[384 + tid];

        // write unnormalized w + stage split-bf16
        #pragma unroll
        for (int mi = 0; mi < 4; mi++) {
            const int rowA = wm * 64 + mi * 16 + quad, rowB = rowA + 8;
            const size_t gA = ((size_t)z * CS + row0 + rowA) * CS + kt;
            const size_t gB = ((size_t)z * CS + row0 + rowB) * CS + kt;
            #pragma unroll
            for (int ni = 0; ni < 4; ni++) {
                const int kl = wn * 32 + ni * 8 + tq * 2;
                const float w0 = sacc[mi][ni][0], w1 = sacc[mi][ni][1];
                const float w2 = sacc[mi][ni][2], w3 = sacc[mi][ni][3];
                *(float2*)&attn[gA + kl] = make_float2(w0, w1);
                *(float2*)&attn[gB + kl] = make_float2(w2, w3);
                __nv_bfloat16 h0, l0, h1, l1;
                split1(w0, h0, l0); split1(w1, h1, l1);
                *(uint32_t*)&Whi[rowA * PW + kl] = bf2u(__halves2bfloat162(h0, h1));
                *(uint32_t*)&Wlo[rowA * PW + kl] = bf2u(__halves2bfloat162(l0, l1));
                split1(w2, h0, l0); split1(w3, h1, l1);
                *(uint32_t*)&Whi[rowB * PW + kl] = bf2u(__halves2bfloat162(h0, h1));
                *(uint32_t*)&Wlo[rowB * PW + kl] = bf2u(__halves2bfloat162(l0, l1));
            }
        }
        __syncthreads();

        // ctx_un += W @ V
        #pragma unroll
        for (int k0 = 0; k0 < 128; k0 += 16) {
            uint32_t ah[4][4], al[4][4], bh[2][2], bl[2][2];
            #pragma unroll
            for (int mi = 0; mi < 4; mi++) {
                const int r0 = wm * 64 + mi * 16 + quad;
                const __nv_bfloat16* p = Whi + r0 * PW + k0 + tq * 2;
                const __nv_bfloat16* q = Wlo + r0 * PW + k0 + tq * 2;
                ah[mi][0] = *(const uint32_t*)p;
                ah[mi][1] = *(const uint32_t*)(p + 8 * PW);
                ah[mi][2] = *(const uint32_t*)(p + 8);
                ah[mi][3] = *(const uint32_t*)(p + 8 * PW + 8);
                al[mi][0] = *(const uint32_t*)q;
                al[mi][1] = *(const uint32_t*)(q + 8 * PW);
                al[mi][2] = *(const uint32_t*)(q + 8);
                al[mi][3] = *(const uint32_t*)(q + 8 * PW + 8);
            }
            #pragma unroll
            for (int ni = 0; ni < 2; ni++) {
                const int n0 = wn * 16 + ni * 8 + quad;
                const __nv_bfloat16* p = Vhi + n0 * PW + k0 + tq * 2;
                const __nv_bfloat16* q = Vlo + n0 * PW + k0 + tq * 2;
                bh[ni][0] = *(const uint32_t*)p;
                bh[ni][1] = *(const uint32_t*)(p + 8);
                bl[ni][0] = *(const uint32_t*)q;
                bl[ni][1] = *(const uint32_t*)(q + 8);
            }
            #pragma unroll
            for (int mi = 0; mi < 4; mi++)
                #pragma unroll
                for (int ni = 0; ni < 2; ni++) mma16816(cacc[mi][ni], ah[mi], bh[ni]);
            #pragma unroll
            for (int mi = 0; mi < 4; mi++)
                #pragma unroll
                for (int ni = 0; ni < 2; ni++) mma16816(cacc[mi][ni], al[mi], bh[ni]);
            #pragma unroll
            for (int mi = 0; mi < 4; mi++)
                #pragma unroll
                for (int ni = 0; ni < 2; ni++) mma16816(cacc[mi][ni], ah[mi], bl[ni]);
        }
    }

    __syncthreads();
    if (tid < 128) sm_aux[tid] = 1.f / sm_sum[tid];
    __syncthreads();

    // store ctx = ctx_un * inv_sum as split-bf16 in [b,s,h,dk]
    const int b = z >> 4, h = z & (CH - 1);
    #pragma unroll
    for (int mi = 0; mi < 4; mi++) {
        const int rloc = wm * 64 + mi * 16 + quad;
        const int q0 = row0 + rloc;
        const float iA = sm_aux[rloc], iB = sm_aux[rloc + 8];
        #pragma unroll
        for (int ni = 0; ni < 2; ni++) {
            const int dk = wn * 16 + ni * 8 + tq * 2;
            const size_t i0 = (((size_t)b * CS + q0) * CH + h) * CDK + dk;
            const size_t i1 = (((size_t)b * CS + q0 + 8) * CH + h) * CDK + dk;
            __nv_bfloat16 h0, l0, h1, l1;
            split1(cacc[mi][ni][0] * iA, h0, l0); split1(cacc[mi][ni][1] * iA, h1, l1);
            *(uint32_t*)&BF(gChi_)[i0] = bf2u(__halves2bfloat162(h0, h1));
            *(uint32_t*)&BF(gClo_)[i0] = bf2u(__halves2bfloat162(l0, l1));
            split1(cacc[mi][ni][2] * iB, h0, l0); split1(cacc[mi][ni][3] * iB, h1, l1);
            *(uint32_t*)&BF(gChi_)[i1] = bf2u(__halves2bfloat162(h0, h1));
            *(uint32_t*)&BF(gClo_)[i1] = bf2u(__halves2bfloat162(l0, l1));
        }
    }

    // rescale this block's attn rows (L2-warm)
    {
        const int c4n = (qt + 1) * 32;
        for (int r = wid; r < 128; r += 8) {
            const float inv = sm_aux[r];
            float4* base = (float4*)&attn[((size_t)z * CS + row0 + r) * CS];
            for (int c = lane; c < c4n; c += 32) {
                float4 v = base[c];
                base[c] = make_float4(v.x * inv, v.y * inv, v.z * inv, v.w * inv);
            }
        }
    }
}

// ---------------------------------------------------------------------------
extern "C" void kernel_launch(void* const* d_in, const int* in_sizes, int n_in,
                              void* d_out, int out_size)
{
    const float* query = (const float*)d_in[0];
    const float* key   = (const float*)d_in[1];
    const float* value = (const float*)d_in[2];
    // d_in[3] = mask (causal by construction; unused)
    const float* w_q = (const float*)d_in[4];
    const float* w_k = (const float*)d_in[5];
    const float* w_v = (const float*)d_in[6];
    const float* w_o = (const float*)d_in[7];
    const float* b_o = (const float*)d_in[8];

    float* out = (float*)d_out;
    const int attn_in_out = ((size_t)out_size >= OUT_ELEMS + ATTN_ELEMS) ? 1 : 0;
    float* attn_ptr = attn_in_out ? (out + OUT_ELEMS) : nullptr;
    const int use_internal = attn_in_out ? 0 : 1;

    cudaFuncSetAttribute(proj_mma,    cudaFuncAttributeMaxDynamicSharedMemorySize, GEMM_SMEM);
    cudaFuncSetAttribute(outproj_mma, cudaFuncAttributeMaxDynamicSharedMemorySize, GEMM_SMEM);
    cudaFuncSetAttribute(fused_attn,  cudaFuncAttributeMaxDynamicSharedMemorySize, SMEM_FUSED);

    // 0. pre-split inputs + weights to hi/lo bf16
    convert_split<<<dim3(4096, 7), 256>>>(query, key, value, w_q, w_k, w_v, w_o);

    // 1. Q/K/V projections (cp.async-pipelined mainloop; V stored transposed)
    proj_mma<<<dim3(CD/128, CM/128, 3), 256, GEMM_SMEM>>>();

    // 2. fused single-pass attention
    fused_attn<<<dim3(16, CB*CH), 256, SMEM_FUSED>>>(attn_ptr, use_internal);

    // 3. output projection + bias (cp.async-pipelined mainloop)
    outproj_mma<<<dim3(CD/128, CM/128), 256, GEMM_SMEM>>>(b_o, out);
}

// round 17
// speedup vs baseline: 1.1566x; 1.0258x over previous
#include <cuda_runtime.h>
#include <cuda_bf16.h>
#include <stdint.h>

// Problem constants
#define CB 2
#define CS 2048
#define CD 1024
#define CH 16
#define CDK 64
#define CM (CB*CS)            // 4096 rows in the projection GEMMs

static const size_t OUT_ELEMS  = (size_t)CB*CS*CD;       // 4,194,304
static const size_t ATTN_ELEMS = (size_t)CB*CH*CS*CS;    // 134,217,728

// ---------------------------------------------------------------------------
// Scratch (device globals; uint4-typed for 16B alignment of bf16 views)
// ---------------------------------------------------------------------------
__device__ float g_attn[(size_t)CB*CH*CS*CS];            // fallback attn buffer

__device__ uint4 gXhi_[(size_t)3*CM*CD/8], gXlo_[(size_t)3*CM*CD/8];   // inputs q,k,v
__device__ uint4 gWhi_[(size_t)4*CD*CD/8], gWlo_[(size_t)4*CD*CD/8];   // wq,wk,wv,wo
__device__ uint4 gQhi_[(size_t)CB*CH*CS*CDK/8], gQlo_[(size_t)CB*CH*CS*CDK/8];
__device__ uint4 gKhi_[(size_t)CB*CH*CS*CDK/8], gKlo_[(size_t)CB*CH*CS*CDK/8];
__device__ uint4 gVthi_[(size_t)CB*CH*CS*CDK/8], gVtlo_[(size_t)CB*CH*CS*CDK/8]; // [h][dk][s]
__device__ uint4 gChi_[(size_t)CB*CS*CD/8], gClo_[(size_t)CB*CS*CD/8];           // ctx

#define BF(p) ((__nv_bfloat16*)(p))

// ===========================================================================
// mma.sync bf16 + cp.async helpers (baseline PTX — legal on compute_103)
// ===========================================================================
__device__ __forceinline__ uint32_t bf2u(__nv_bfloat162 v) { return *reinterpret_cast<uint32_t*>(&v); }

__device__ __forceinline__ void mma16816(float* c, const uint32_t* a, const uint32_t* b) {
    asm volatile(
        "mma.sync.aligned.m16n8k16.row.col.f32.bf16.bf16.f32 "
        "{%0,%1,%2,%3}, {%4,%5,%6,%7}, {%8,%9}, {%0,%1,%2,%3};"
        : "+f"(c[0]), "+f"(c[1]), "+f"(c[2]), "+f"(c[3])
        : "r"(a[0]), "r"(a[1]), "r"(a[2]), "r"(a[3]), "r"(b[0]), "r"(b[1]));
}

__device__ __forceinline__ uint32_t smem_u32(const void* p) {
    uint32_t a;
    asm("{ .reg .u64 t; cvta.to.shared.u64 t, %1; cvt.u32.u64 %0, t; }" : "=r"(a) : "l"(p));
    return a;
}
__device__ __forceinline__ void cp_async16(uint32_t saddr, const void* gptr) {
    asm volatile("cp.async.cg.shared.global [%0], [%1], 16;" :: "r"(saddr), "l"(gptr));
}
__device__ __forceinline__ void cp_commit() { asm volatile("cp.async.commit_group;" ::: "memory"); }
template <int N> __device__ __forceinline__ void cp_wait() {
    asm volatile("cp.async.wait_group %0;" :: "n"(N) : "memory");
}

__device__ __forceinline__ void split4(float4 v, uint2& hi, uint2& lo) {
    __nv_bfloat16 h0 = __float2bfloat16_rn(v.x);
    __nv_bfloat16 h1 = __float2bfloat16_rn(v.y);
    __nv_bfloat16 h2 = __float2bfloat16_rn(v.z);
    __nv_bfloat16 h3 = __float2bfloat16_rn(v.w);
    float l0 = v.x - __bfloat162float(h0);
    float l1 = v.y - __bfloat162float(h1);
    float l2 = v.z - __bfloat162float(h2);
    float l3 = v.w - __bfloat162float(h3);
    hi = make_uint2(bf2u(__halves2bfloat162(h0, h1)), bf2u(__halves2bfloat162(h2, h3)));
    lo = make_uint2(bf2u(__halves2bfloat162(__float2bfloat16_rn(l0), __float2bfloat16_rn(l1))),
                    bf2u(__halves2bfloat162(__float2bfloat16_rn(l2), __float2bfloat16_rn(l3))));
}
__device__ __forceinline__ void split1(float v, __nv_bfloat16& hi, __nv_bfloat16& lo) {
    hi = __float2bfloat16_rn(v);
    lo = __float2bfloat16_rn(v - __bfloat162float(hi));
}

// ===========================================================================
// Kernel 0: pre-split inputs (z=0..2) and weights (z=3..6) to hi/lo bf16.
// ===========================================================================
__global__ __launch_bounds__(256) void convert_split(
    const float* __restrict__ q, const float* __restrict__ k, const float* __restrict__ v,
    const float* __restrict__ wq, const float* __restrict__ wk, const float* __restrict__ wv,
    const float* __restrict__ wo)
{
    const int z = blockIdx.y;
    const float* srcs[7] = {q, k, v, wq, wk, wv, wo};
    const int nvec = (z < 3 ? CM * CD : CD * CD) / 4;
    const int idx = blockIdx.x * 256 + threadIdx.x;
    if (idx >= nvec) return;
    float4 val = ((const float4*)srcs[z])[idx];
    uint2 hi, lo;
    split4(val, hi, lo);
    uint2* dh;
    uint2* dl;
    if (z < 3) {
        dh = (uint2*)(BF(gXhi_) + (size_t)z * CM * CD);
        dl = (uint2*)(BF(gXlo_) + (size_t)z * CM * CD);
    } else {
        dh = (uint2*)(BF(gWhi_) + (size_t)(z - 3) * CD * CD);
        dl = (uint2*)(BF(gWlo_) + (size_t)(z - 3) * CD * CD);
    }
    dh[idx] = hi;
    dl[idx] = lo;
}

// ===========================================================================
// Split-bf16 GEMM core: cp.async 2-stage pipeline (LDGSTS, no reg staging).
// acc[128,128] = A[128,K] * B[128,K]^T.  8 warps 2x4, warp tile 64x32.
// ===========================================================================
#define PADK 40
#define SB_BYTES (128 * PADK * 2)          // one hi/lo array, bytes
#define GEMM_SMEM (8 * SB_BYTES)           // 2 stages x 4 arrays

__device__ __forceinline__ void mma_gemm_core_bf(
    const __nv_bfloat16* __restrict__ Ahi_g, const __nv_bfloat16* __restrict__ Alo_g,
    const __nv_bfloat16* __restrict__ Bhi_g, const __nv_bfloat16* __restrict__ Blo_g,
    int ld, int kTotal, __nv_bfloat16* sm, float acc[4][4][4])
{
    const int tid  = threadIdx.x;
    const int wid  = tid >> 5, lane = tid & 31;
    const int wm   = wid & 1,  wn   = wid >> 1;
    const int quad = lane >> 2, tq  = lane & 3;

    const int lrow = tid >> 1;            // tile row loaded by this thread
    const int lk16 = (tid & 1) * 16;      // 16-col half of BK=32

    const __nv_bfloat16* ah = Ahi_g + (size_t)lrow * ld + lk16;
    const __nv_bfloat16* al = Alo_g + (size_t)lrow * ld + lk16;
    const __nv_bfloat16* bh = Bhi_g + (size_t)lrow * ld + lk16;
    const __nv_bfloat16* bl = Blo_g + (size_t)lrow * ld + lk16;

    const uint32_t sbase = smem_u32(sm);
    const uint32_t soff  = (uint32_t)(lrow * PADK + lk16) * 2;   // bytes, 16B-aligned

    #pragma unroll
    for (int mi = 0; mi < 4; mi++)
        #pragma unroll
        for (int ni = 0; ni < 4; ni++)
            #pragma unroll
            for (int r = 0; r < 4; r++) acc[mi][ni][r] = 0.f;

    const int nch = kTotal / 32;

    // prefetch chunk 0 into stage 0
    {
        const uint32_t s0 = sbase + soff;
        cp_async16(s0,                ah);
        cp_async16(s0 + 16,           ah + 8);
        cp_async16(s0 + SB_BYTES,     al);
        cp_async16(s0 + SB_BYTES+16,  al + 8);
        cp_async16(s0 + 2*SB_BYTES,   bh);
        cp_async16(s0 + 2*SB_BYTES+16,bh + 8);
        cp_async16(s0 + 3*SB_BYTES,   bl);
        cp_async16(s0 + 3*SB_BYTES+16,bl + 8);
        cp_commit();
    }

    const int STRIDE = 128 * PADK;
    for (int c = 0; c < nch; c++) {
        if (c + 1 < nch) {     // prefetch next chunk into the other stage
            const uint32_t s1 = sbase + ((c + 1) & 1) * 4 * SB_BYTES + soff;
            const int g = (c + 1) * 32;
            cp_async16(s1,                 ah + g);
            cp_async16(s1 + 16,            ah + g + 8);
            cp_async16(s1 + SB_BYTES,      al + g);
            cp_async16(s1 + SB_BYTES+16,   al + g + 8);
            cp_async16(s1 + 2*SB_BYTES,    bh + g);
            cp_async16(s1 + 2*SB_BYTES+16, bh + g + 8);
            cp_async16(s1 + 3*SB_BYTES,    bl + g);
            cp_async16(s1 + 3*SB_BYTES+16, bl + g + 8);
            cp_commit();
            cp_wait<1>();      // chunk c arrived; c+1 in flight
        } else {
            cp_wait<0>();
        }
        __syncthreads();

        __nv_bfloat16* Ahi = sm + (c & 1) * 4 * STRIDE;
        __nv_bfloat16* Alo = Ahi + STRIDE;
        __nv_bfloat16* Bhi = Alo + STRIDE;
        __nv_bfloat16* Blo = Bhi + STRIDE;

        #pragma unroll
        for (int k0 = 0; k0 < 32; k0 += 16) {
            uint32_t fa[4][4], fb[4][4], gb[4][2], gl[4][2];
            #pragma unroll
            for (int mi = 0; mi < 4; mi++) {
                const int r0 = wm * 64 + mi * 16 + quad;
                const __nv_bfloat16* p = Ahi + r0 * PADK + k0 + tq * 2;
                const __nv_bfloat16* q = Alo + r0 * PADK + k0 + tq * 2;
                fa[mi][0] = *(const uint32_t*)p;
                fa[mi][1] = *(const uint32_t*)(p + 8 * PADK);
                fa[mi][2] = *(const uint32_t*)(p + 8);
                fa[mi][3] = *(const uint32_t*)(p + 8 * PADK + 8);
                fb[mi][0] = *(const uint32_t*)q;
                fb[mi][1] = *(const uint32_t*)(q + 8 * PADK);
                fb[mi][2] = *(const uint32_t*)(q + 8);
                fb[mi][3] = *(const uint32_t*)(q + 8 * PADK + 8);
            }
            #pragma unroll
            for (int ni = 0; ni < 4; ni++) {
                const int n0 = wn * 32 + ni * 8 + quad;
                const __nv_bfloat16* p = Bhi + n0 * PADK + k0 + tq * 2;
                const __nv_bfloat16* q = Blo + n0 * PADK + k0 + tq * 2;
                gb[ni][0] = *(const uint32_t*)p;
                gb[ni][1] = *(const uint32_t*)(p + 8);
                gl[ni][0] = *(const uint32_t*)q;
                gl[ni][1] = *(const uint32_t*)(q + 8);
            }
            #pragma unroll
            for (int mi = 0; mi < 4; mi++)
                #pragma unroll
                for (int ni = 0; ni < 4; ni++) mma16816(acc[mi][ni], fa[mi], gb[ni]);
            #pragma unroll
            for (int mi = 0; mi < 4; mi++)
                #pragma unroll
                for (int ni = 0; ni < 4; ni++) mma16816(acc[mi][ni], fb[mi], gb[ni]);
            #pragma unroll
            for (int mi = 0; mi < 4; mi++)
                #pragma unroll
                for (int ni = 0; ni < 4; ni++) mma16816(acc[mi][ni], fa[mi], gl[ni]);
        }
        __syncthreads();       // all warps done reading stage (c&1) before refill
    }
}

// ---------------------------------------------------------------------------
// Kernel 1: Q/K/V projections.  Q/K stored split-bf16 [h][s][dk];
// V stored split-bf16 TRANSPOSED [h][dk][s] via smem transpose.
// __launch_bounds__(256, 2): cap regs at 128 so 2 CTAs/SM co-reside.
// ---------------------------------------------------------------------------
__global__ __launch_bounds__(256, 2) void proj_mma()
{
    extern __shared__ __nv_bfloat16 smg[];

    const int z = blockIdx.z;
    const int row0 = blockIdx.y * 128, col0 = blockIdx.x * 128;

    float acc[4][4][4];
    mma_gemm_core_bf(
        BF(gXhi_) + (size_t)z * CM * CD + (size_t)row0 * CD,
        BF(gXlo_) + (size_t)z * CM * CD + (size_t)row0 * CD,
        BF(gWhi_) + (size_t)z * CD * CD + (size_t)col0 * CD,
        BF(gWlo_) + (size_t)z * CD * CD + (size_t)col0 * CD,
        CD, CD, smg, acc);

    const int tid  = threadIdx.x;
    const int wid  = tid >> 5, lane = tid & 31;
    const int wm   = wid & 1, wn = wid >> 1;
    const int quad = lane >> 2, tq = lane & 3;

    if (z < 2) {
        __nv_bfloat16* Ohi = z == 0 ? BF(gQhi_) : BF(gKhi_);
        __nv_bfloat16* Olo = z == 0 ? BF(gQlo_) : BF(gKlo_);
        #pragma unroll
        for (int mi = 0; mi < 4; mi++) {
            const int m = row0 + wm * 64 + mi * 16 + quad;
            const int b = m >> 11, s = m & (CS - 1);
            #pragma unroll
            for (int ni = 0; ni < 4; ni++) {
                const int n  = col0 + wn * 32 + ni * 8 + tq * 2;
                const int h  = n >> 6, dk = n & (CDK - 1);
                const size_t i0 = (((size_t)(b * CH + h)) * CS + s)     * CDK + dk;
                const size_t i1 = (((size_t)(b * CH + h)) * CS + s + 8) * CDK + dk;
                __nv_bfloat16 h0, l0, h1, l1;
                split1(acc[mi][ni][0], h0, l0); split1(acc[mi][ni][1], h1, l1);
                *(uint32_t*)&Ohi[i0] = bf2u(__halves2bfloat162(h0, h1));
                *(uint32_t*)&Olo[i0] = bf2u(__halves2bfloat162(l0, l1));
                split1(acc[mi][ni][2], h0, l0); split1(acc[mi][ni][3], h1, l1);
                *(uint32_t*)&Ohi[i1] = bf2u(__halves2bfloat162(h0, h1));
                *(uint32_t*)&Olo[i1] = bf2u(__halves2bfloat162(l0, l1));
            }
        }
    } else {
        // V: transpose through smem scratch (128 n x 128 m fp32, stride 132)
        __syncthreads();                 // all warps done with GEMM smem
        float* ts = (float*)smg;
        #pragma unroll
        for (int mi = 0; mi < 4; mi++) {
            const int ml = wm * 64 + mi * 16 + quad;
            #pragma unroll
            for (int ni = 0; ni < 4; ni++) {
                const int nl = wn * 32 + ni * 8 + tq * 2;
                ts[nl * 132 + ml]           = acc[mi][ni][0];
                ts[(nl + 1) * 132 + ml]     = acc[mi][ni][1];
                ts[nl * 132 + ml + 8]       = acc[mi][ni][2];
                ts[(nl + 1) * 132 + ml + 8] = acc[mi][ni][3];
            }
        }
        __syncthreads();
        const int r    = tid >> 1;           // local n (dk-ish)
        const int half = tid & 1;            // m half
        const int ng   = col0 + r;
        const int h    = ng >> 6, dkv = ng & (CDK - 1);
        const int b    = row0 >> 11;
        const size_t obase = ((size_t)(b * CH + h) * CDK + dkv) * CS + (row0 & (CS - 1)) + half * 64;
        #pragma unroll
        for (int j = 0; j < 16; j++) {
            float4 v = *(float4*)&ts[r * 132 + half * 64 + j * 4];
            uint2 hi, lo;
            split4(v, hi, lo);
            *(uint2*)(BF(gVthi_) + obase + j * 4) = hi;
            *(uint2*)(BF(gVtlo_) + obase + j * 4) = lo;
        }
    }
}

// ---------------------------------------------------------------------------
// Kernel 3: output projection.  out = ctx @ Wo^T + bias (ctx preconverted).
// __launch_bounds__(256, 2): cap regs at 128 so 2 CTAs/SM co-reside.
// ---------------------------------------------------------------------------
__global__ __launch_bounds__(256, 2) void outproj_mma(
    const float* __restrict__ bias, float* __restrict__ Out)
{
    extern __shared__ __nv_bfloat16 smg[];

    const int row0 = blockIdx.y * 128, col0 = blockIdx.x * 128;
    float acc[4][4][4];
    mma_gemm_core_bf(
        BF(gChi_) + (size_t)row0 * CD, BF(gClo_) + (size_t)row0 * CD,
        BF(gWhi_) + (size_t)3 * CD * CD + (size_t)col0 * CD,
        BF(gWlo_) + (size_t)3 * CD * CD + (size_t)col0 * CD,
        CD, CD, smg, acc);

    const int wid  = threadIdx.x >> 5, lane = threadIdx.x & 31;
    const int wm   = wid & 1, wn = wid >> 1;
    const int quad = lane >> 2, tq = lane & 3;

    #pragma unroll
    for (int mi = 0; mi < 4; mi++) {
        const int m = row0 + wm * 64 + mi * 16 + quad;
        #pragma unroll
        for (int ni = 0; ni < 4; ni++) {
            const int n = col0 + wn * 32 + ni * 8 + tq * 2;
            const float2 bv = *(const float2*)(bias + n);
            *(float2*)&Out[(size_t)m * CD + n] =
                make_float2(acc[mi][ni][0] + bv.x, acc[mi][ni][1] + bv.y);
            *(float2*)&Out[(size_t)(m + 8) * CD + n] =
                make_float2(acc[mi][ni][2] + bv.x, acc[mi][ni][3] + bv.y);
        }
    }
}

// ===========================================================================
// Kernel 2: fused scores + softmax + context — single pass, preconverted
// bf16 Q/K/V (V pre-transposed), ctx written as split-bf16.
// 3 barriers/chunk: row-sum accumulation shares the W-staging barrier.
// ===========================================================================
#define PK 72      // padded row stride for Q/K tiles (64 + 8)
#define PW 136     // padded row stride for W/V^T tiles (128 + 8)
#define ASCALE 0.125f
#define SMEM_FUSED 181248

__device__ __forceinline__ void s_mma_64(
    const __nv_bfloat16* Qhi, const __nv_bfloat16* Qlo,
    const __nv_bfloat16* Khi, const __nv_bfloat16* Klo,
    int wm, int wn, int quad, int tq, float sacc[4][4][4])
{
    #pragma unroll
    for (int mi = 0; mi < 4; mi++)
        #pragma unroll
        for (int ni = 0; ni < 4; ni++)
            #pragma unroll
            for (int r = 0; r < 4; r++) sacc[mi][ni][r] = 0.f;

    #pragma unroll
    for (int k0 = 0; k0 < 64; k0 += 16) {
        uint32_t ah[4][4], al[4][4], bh[4][2], bl[4][2];
        #pragma unroll
        for (int mi = 0; mi < 4; mi++) {
            const int r0 = wm * 64 + mi * 16 + quad;
            const __nv_bfloat16* p = Qhi + r0 * PK + k0 + tq * 2;
            const __nv_bfloat16* q = Qlo + r0 * PK + k0 + tq * 2;
            ah[mi][0] = *(const uint32_t*)p;
            ah[mi][1] = *(const uint32_t*)(p + 8 * PK);
            ah[mi][2] = *(const uint32_t*)(p + 8);
            ah[mi][3] = *(const uint32_t*)(p + 8 * PK + 8);
            al[mi][0] = *(const uint32_t*)q;
            al[mi][1] = *(const uint32_t*)(q + 8 * PK);
            al[mi][2] = *(const uint32_t*)(q + 8);
            al[mi][3] = *(const uint32_t*)(q + 8 * PK + 8);
        }
        #pragma unroll
        for (int ni = 0; ni < 4; ni++) {
            const int n0 = wn * 32 + ni * 8 + quad;
            const __nv_bfloat16* p = Khi + n0 * PK + k0 + tq * 2;
            const __nv_bfloat16* q = Klo + n0 * PK + k0 + tq * 2;
            bh[ni][0] = *(const uint32_t*)p;
            bh[ni][1] = *(const uint32_t*)(p + 8);
            bl[ni][0] = *(const uint32_t*)q;
            bl[ni][1] = *(const uint32_t*)(q + 8);
        }
        #pragma unroll
        for (int mi = 0; mi < 4; mi++)
            #pragma unroll
            for (int ni = 0; ni < 4; ni++) mma16816(sacc[mi][ni], ah[mi], bh[ni]);
        #pragma unroll
        for (int mi = 0; mi < 4; mi++)
            #pragma unroll
            for (int ni = 0; ni < 4; ni++) mma16816(sacc[mi][ni], al[mi], bh[ni]);
        #pragma unroll
        for (int mi = 0; mi < 4; mi++)
            #pragma unroll
            for (int ni = 0; ni < 4; ni++) mma16816(sacc[mi][ni], ah[mi], bl[ni]);
    }
}

__global__ __launch_bounds__(256) void fused_attn(float* __restrict__ attn_out, int use_internal)
{
    float* attn = use_internal ? g_attn : attn_out;

    extern __shared__ char dynsm[];
    float* sm_sum  = (float*)dynsm;            // [128] running row sum
    float* sm_aux  = sm_sum + 128;             // [128] 1/sum
    float* sm_part = sm_aux + 128;             // [4][128] partials
    __nv_bfloat16* Qhi = (__nv_bfloat16*)(sm_part + 512);
    __nv_bfloat16* Qlo = Qhi + 128 * PK;
    __nv_bfloat16* Khi = Qlo + 128 * PK;
    __nv_bfloat16* Klo = Khi + 128 * PK;
    __nv_bfloat16* Whi = Klo + 128 * PK;
    __nv_bfloat16* Wlo = Whi + 128 * PW;
    __nv_bfloat16* Vhi = Wlo + 128 * PW;
    __nv_bfloat16* Vlo = Vhi + 64 * PW;

    const int z    = blockIdx.y;
    const int qt   = 15 - blockIdx.x;          // big tiles first
    const int row0 = qt * 128;
    const __nv_bfloat16* Qhg = BF(gQhi_) + (size_t)z * CS * CDK;
    const __nv_bfloat16* Qlg = BF(gQlo_) + (size_t)z * CS * CDK;
    const __nv_bfloat16* Khg = BF(gKhi_) + (size_t)z * CS * CDK;
    const __nv_bfloat16* Klg = BF(gKlo_) + (size_t)z * CS * CDK;
    const __nv_bfloat16* Vhg = BF(gVthi_) + (size_t)z * CDK * CS;
    const __nv_bfloat16* Vlg = BF(gVtlo_) + (size_t)z * CDK * CS;

    const int tid  = threadIdx.x;
    const int wid  = tid >> 5, lane = tid & 31;
    const int wm   = wid & 1,  wn   = wid >> 1;
    const int quad = lane >> 2, tq  = lane & 3;
    const int lrow = tid >> 1, lkq = (tid & 1) * 32;
    const int vr   = tid >> 2, vq  = tid & 3;

    // zero-fill right of causal edge
    {
        const int kend = row0 + 128;
        const int rem4 = (CS - kend) >> 2;
        const int total = 128 * rem4;
        const float4 z4 = make_float4(0.f, 0.f, 0.f, 0.f);
        for (int idx = tid; idx < total; idx += 256) {
            const int r = idx / rem4, c4 = idx - r * rem4;
            *(float4*)&attn[((size_t)z * CS + row0 + r) * CS + kend + c4 * 4] = z4;
        }
    }

    if (tid < 128) sm_sum[tid] = 0.f;

    // load Q tile (bf16 copies)
    {
        const __nv_bfloat16* qh = Qhg + (size_t)(row0 + lrow) * CDK + lkq;
        const __nv_bfloat16* ql = Qlg + (size_t)(row0 + lrow) * CDK + lkq;
        #pragma unroll
        for (int j = 0; j < 4; j++) {
            *(uint4*)(Qhi + lrow * PK + lkq + j * 8) = *(const uint4*)(qh + j * 8);
            *(uint4*)(Qlo + lrow * PK + lkq + j * 8) = *(const uint4*)(ql + j * 8);
        }
    }
    __syncthreads();

    float cacc[4][2][4];
    #pragma unroll
    for (int mi = 0; mi < 4; mi++)
        #pragma unroll
        for (int ni = 0; ni < 2; ni++)
            #pragma unroll
            for (int r = 0; r < 4; r++) cacc[mi][ni][r] = 0.f;

    for (int ck = 0; ck <= qt; ck++) {
        const int kt = ck * 128;
        uint4 kvh[4], kvl[4], vvh[4], vvl[4];
        {
            const __nv_bfloat16* kh = Khg + (size_t)(kt + lrow) * CDK + lkq;
            const __nv_bfloat16* kl = Klg + (size_t)(kt + lrow) * CDK + lkq;
            const __nv_bfloat16* vh = Vhg + (size_t)vr * CS + kt + vq * 32;
            const __nv_bfloat16* vl = Vlg + (size_t)vr * CS + kt + vq * 32;
            #pragma unroll
            for (int j = 0; j < 4; j++) {
                kvh[j] = *(const uint4*)(kh + j * 8);
                kvl[j] = *(const uint4*)(kl + j * 8);
                vvh[j] = *(const uint4*)(vh + j * 8);
                vvl[j] = *(const uint4*)(vl + j * 8);
            }
        }
        __syncthreads();   // prior chunk's MMAs done reading K/V/W smem
        #pragma unroll
        for (int j = 0; j < 4; j++) {
            *(uint4*)(Khi + lrow * PK + lkq + j * 8) = kvh[j];
            *(uint4*)(Klo + lrow * PK + lkq + j * 8) = kvl[j];
            *(uint4*)(Vhi + vr * PW + vq * 32 + j * 8) = vvh[j];
            *(uint4*)(Vlo + vr * PW + vq * 32 + j * 8) = vvl[j];
        }
        __syncthreads();

        float sacc[4][4][4];
        s_mma_64(Qhi, Qlo, Khi, Klo, wm, wn, quad, tq, sacc);

        // w = exp(scale*s), masked lanes exact 0 (diagonal chunk only)
        const int diag = (ck == qt);
        #pragma unroll
        for (int mi = 0; mi < 4; mi++) {
            const int q0A = row0 + wm * 64 + mi * 16 + quad;
            const int q0B = q0A + 8;
            #pragma unroll
            for (int ni = 0; ni < 4; ni++) {
                const int kg = kt + wn * 32 + ni * 8 + tq * 2;
                float w0 = __expf(sacc[mi][ni][0] * ASCALE);
                float w1 = __expf(sacc[mi][ni][1] * ASCALE);
                float w2 = __expf(sacc[mi][ni][2] * ASCALE);
                float w3 = __expf(sacc[mi][ni][3] * ASCALE);
                if (diag) {
                    if (kg     > q0A) w0 = 0.f;
                    if (kg + 1 > q0A) w1 = 0.f;
                    if (kg     > q0B) w2 = 0.f;
                    if (kg + 1 > q0B) w3 = 0.f;
                }
                sacc[mi][ni][0] = w0; sacc[mi][ni][1] = w1;
                sacc[mi][ni][2] = w2; sacc[mi][ni][3] = w3;
            }
        }

        // partial row sums -> sm_part (no barrier yet; shares W-staging barrier)
        #pragma unroll
        for (int mi = 0; mi < 4; mi++) {
            const int rowA = wm * 64 + mi * 16 + quad, rowB = rowA + 8;
            float sA = 0.f, sB = 0.f;
            #pragma unroll
            for (int ni = 0; ni < 4; ni++) {
                sA += sacc[mi][ni][0] + sacc[mi][ni][1];
                sB += sacc[mi][ni][2] + sacc[mi][ni][3];
            }
            #pragma unroll
            for (int o = 1; o <= 2; o <<= 1) {
                sA += __shfl_xor_sync(0xffffffffu, sA, o);
                sB += __shfl_xor_sync(0xffffffffu, sB, o);
            }
            if (tq == 0) { sm_part[wn * 128 + rowA] = sA; sm_part[wn * 128 + rowB] = sB; }
        }

        // write unnormalized w to gmem + stage split-bf16 for ctx MMA
        #pragma unroll
        for (int mi = 0; mi < 4; mi++) {
            const int rowA = wm * 64 + mi * 16 + quad, rowB = rowA + 8;
            const size_t gA = ((size_t)z * CS + row0 + rowA) * CS + kt;
            const size_t gB = ((size_t)z * CS + row0 + rowB) * CS + kt;
            #pragma unroll
            for (int ni = 0; ni < 4; ni++) {
                const int kl = wn * 32 + ni * 8 + tq * 2;
                const float w0 = sacc[mi][ni][0], w1 = sacc[mi][ni][1];
                const float w2 = sacc[mi][ni][2], w3 = sacc[mi][ni][3];
                *(float2*)&attn[gA + kl] = make_float2(w0, w1);
                *(float2*)&attn[gB + kl] = make_float2(w2, w3);
                __nv_bfloat16 h0, l0, h1, l1;
                split1(w0, h0, l0); split1(w1, h1, l1);
                *(uint32_t*)&Whi[rowA * PW + kl] = bf2u(__halves2bfloat162(h0, h1));
                *(uint32_t*)&Wlo[rowA * PW + kl] = bf2u(__halves2bfloat162(l0, l1));
                split1(w2, h0, l0); split1(w3, h1, l1);
                *(uint32_t*)&Whi[rowB * PW + kl] = bf2u(__halves2bfloat162(h0, h1));
                *(uint32_t*)&Wlo[rowB * PW + kl] = bf2u(__halves2bfloat162(l0, l1));
            }
        }
        __syncthreads();   // W staged AND sm_part visible

        if (tid < 128)
            sm_sum[tid] += sm_part[tid] + sm_part[128 + tid] + sm_part[256 + tid] + sm_part[384 + tid];

        // ctx_un += W @ V
        #pragma unroll
        for (int k0 = 0; k0 < 128; k0 += 16) {
            uint32_t ah[4][4], al[4][4], bh[2][2], bl[2][2];
            #pragma unroll
            for (int mi = 0; mi < 4; mi++) {
                const int r0 = wm * 64 + mi * 16 + quad;
                const __nv_bfloat16* p = Whi + r0 * PW + k0 + tq * 2;
                const __nv_bfloat16* q = Wlo + r0 * PW + k0 + tq * 2;
                ah[mi][0] = *(const uint32_t*)p;
                ah[mi][1] = *(const uint32_t*)(p + 8 * PW);
                ah[mi][2] = *(const uint32_t*)(p + 8);
                ah[mi][3] = *(const uint32_t*)(p + 8 * PW + 8);
                al[mi][0] = *(const uint32_t*)q;
                al[mi][1] = *(const uint32_t*)(q + 8 * PW);
                al[mi][2] = *(const uint32_t*)(q + 8);
                al[mi][3] = *(const uint32_t*)(q + 8 * PW + 8);
            }
            #pragma unroll
            for (int ni = 0; ni < 2; ni++) {
                const int n0 = wn * 16 + ni * 8 + quad;
                const __nv_bfloat16* p = Vhi + n0 * PW + k0 + tq * 2;
                const __nv_bfloat16* q = Vlo + n0 * PW + k0 + tq * 2;
                bh[ni][0] = *(const uint32_t*)p;
                bh[ni][1] = *(const uint32_t*)(p + 8);
                bl[ni][0] = *(const uint32_t*)q;
                bl[ni][1] = *(const uint32_t*)(q + 8);
            }
            #pragma unroll
            for (int mi = 0; mi < 4; mi++)
                #pragma unroll
                for (int ni = 0; ni < 2; ni++) mma16816(cacc[mi][ni], ah[mi], bh[ni]);
            #pragma unroll
            for (int mi = 0; mi < 4; mi++)
                #pragma unroll
                for (int ni = 0; ni < 2; ni++) mma16816(cacc[mi][ni], al[mi], bh[ni]);
            #pragma unroll
            for (int mi = 0; mi < 4; mi++)
                #pragma unroll
                for (int ni = 0; ni < 2; ni++) mma16816(cacc[mi][ni], ah[mi], bl[ni]);
        }
    }

    __syncthreads();
    if (tid < 128) sm_aux[tid] = 1.f / sm_sum[tid];
    __syncthreads();

    // store ctx = ctx_un * inv_sum as split-bf16 in [b,s,h,dk]
    const int b = z >> 4, h = z & (CH - 1);
    #pragma unroll
    for (int mi = 0; mi < 4; mi++) {
        const int rloc = wm * 64 + mi * 16 + quad;
        const int q0 = row0 + rloc;
        const float iA = sm_aux[rloc], iB = sm_aux[rloc + 8];
        #pragma unroll
        for (int ni = 0; ni < 2; ni++) {
            const int dk = wn * 16 + ni * 8 + tq * 2;
            const size_t i0 = (((size_t)b * CS + q0) * CH + h) * CDK + dk;
            const size_t i1 = (((size_t)b * CS + q0 + 8) * CH + h) * CDK + dk;
            __nv_bfloat16 h0, l0, h1, l1;
            split1(cacc[mi][ni][0] * iA, h0, l0); split1(cacc[mi][ni][1] * iA, h1, l1);
            *(uint32_t*)&BF(gChi_)[i0] = bf2u(__halves2bfloat162(h0, h1));
            *(uint32_t*)&BF(gClo_)[i0] = bf2u(__halves2bfloat162(l0, l1));
            split1(cacc[mi][ni][2] * iB, h0, l0); split1(cacc[mi][ni][3] * iB, h1, l1);
            *(uint32_t*)&BF(gChi_)[i1] = bf2u(__halves2bfloat162(h0, h1));
            *(uint32_t*)&BF(gClo_)[i1] = bf2u(__halves2bfloat162(l0, l1));
        }
    }

    // rescale this block's attn rows (L2-warm)
    {
        const int c4n = (qt + 1) * 32;
        for (int r = wid; r < 128; r += 8) {
            const float inv = sm_aux[r];
            float4* base = (float4*)&attn[((size_t)z * CS + row0 + r) * CS];
            for (int c = lane; c < c4n; c += 32) {
                float4 v = base[c];
                base[c] = make_float4(v.x * inv, v.y * inv, v.z * inv, v.w * inv);
            }
        }
    }
}

// ---------------------------------------------------------------------------
extern "C" void kernel_launch(void* const* d_in, const int* in_sizes, int n_in,
                              void* d_out, int out_size)
{
    const float* query = (const float*)d_in[0];
    const float* key   = (const float*)d_in[1];
    const float* value = (const float*)d_in[2];
    // d_in[3] = mask (causal by construction; unused)
    const float* w_q = (const float*)d_in[4];
    const float* w_k = (const float*)d_in[5];
    const float* w_v = (const float*)d_in[6];
    const float* w_o = (const float*)d_in[7];
    const float* b_o = (const float*)d_in[8];

    float* out = (float*)d_out;
    const int attn_in_out = ((size_t)out_size >= OUT_ELEMS + ATTN_ELEMS) ? 1 : 0;
    float* attn_ptr = attn_in_out ? (out + OUT_ELEMS) : nullptr;
    const int use_internal = attn_in_out ? 0 : 1;

    cudaFuncSetAttribute(proj_mma,    cudaFuncAttributeMaxDynamicSharedMemorySize, GEMM_SMEM);
    cudaFuncSetAttribute(outproj_mma, cudaFuncAttributeMaxDynamicSharedMemorySize, GEMM_SMEM);
    cudaFuncSetAttribute(fused_attn,  cudaFuncAttributeMaxDynamicSharedMemorySize, SMEM_FUSED);

    // 0. pre-split inputs + weights to hi/lo bf16
    convert_split<<<dim3(4096, 7), 256>>>(query, key, value, w_q, w_k, w_v, w_o);

    // 1. Q/K/V projections (cp.async pipeline, 2 CTAs/SM; V stored transposed)
    proj_mma<<<dim3(CD/128, CM/128, 3), 256, GEMM_SMEM>>>();

    // 2. fused single-pass attention (3 barriers/chunk)
    fused_attn<<<dim3(16, CB*CH), 256, SMEM_FUSED>>>(attn_ptr, use_internal);

    // 3. output projection + bias (cp.async pipeline, 2 CTAs/SM)
    outproj_mma<<<dim3(CD/128, CM/128), 256, GEMM_SMEM>>>(b_o, out);
}